// round 2
// baseline (speedup 1.0000x reference)
#include <cuda_runtime.h>
#include <math.h>

#define NN 50000
#define EE 800000
#define CC 40

// ---------------- scratch (device globals; no allocations allowed) ----------------
__device__ float g_bufA[NN * 256];   // feat buffer
__device__ float g_bufB[NN * 256];   // layer output / next input
__device__ float g_el[NN * 4];
__device__ float g_er[NN * 4];
__device__ float g_emax[NN * 4];
__device__ float g_den[NN * 4];
__device__ float g_e[EE * 4];        // per-edge e -> ex

// ---------------- helpers ----------------
__device__ __forceinline__ void atomicMaxF(float* addr, float v) {
    if (v >= 0.f) atomicMax((int*)addr, __float_as_int(v));
    else          atomicMin((unsigned int*)addr, __float_as_uint(v));
}

// ---------------- GEMM: C[M,J] = A[M,K] @ B[K,J] (fp32, tiled) ----------------
template <int BM, int BN, int BK, int TM, int TN>
__global__ __launch_bounds__(256) void sgemm(const float* __restrict__ A,
                                             const float* __restrict__ B,
                                             float* __restrict__ C,
                                             int M, int K, int J) {
    __shared__ float As[BK][BM];
    __shared__ float Bs[BK][BN];
    int tid = threadIdx.x;
    int row0 = blockIdx.y * BM;
    int col0 = blockIdx.x * BN;
    int tx = tid % (BN / TN);
    int ty = tid / (BN / TN);
    float acc[TM][TN];
#pragma unroll
    for (int i = 0; i < TM; i++)
#pragma unroll
        for (int j = 0; j < TN; j++) acc[i][j] = 0.f;

    for (int k0 = 0; k0 < K; k0 += BK) {
        // load A tile (K always a multiple of BK)
        for (int i = tid; i < BM * BK; i += 256) {
            int r = i / BK, c = i % BK;
            int gr = row0 + r;
            As[c][r] = (gr < M) ? A[(size_t)gr * K + (k0 + c)] : 0.f;
        }
        for (int i = tid; i < BK * BN; i += 256) {
            int r = i / BN, c = i % BN;
            int gc = col0 + c;
            Bs[r][c] = (gc < J) ? B[(size_t)(k0 + r) * J + gc] : 0.f;
        }
        __syncthreads();
#pragma unroll
        for (int kk = 0; kk < BK; kk++) {
            float a[TM], b[TN];
#pragma unroll
            for (int i = 0; i < TM; i++) a[i] = As[kk][ty * TM + i];
#pragma unroll
            for (int j = 0; j < TN; j++) b[j] = Bs[kk][tx * TN + j];
#pragma unroll
            for (int i = 0; i < TM; i++)
#pragma unroll
                for (int j = 0; j < TN; j++) acc[i][j] += a[i] * b[j];
        }
        __syncthreads();
    }
#pragma unroll
    for (int i = 0; i < TM; i++) {
        int gr = row0 + ty * TM + i;
        if (gr >= M) continue;
#pragma unroll
        for (int j = 0; j < TN; j++) {
            int gc = col0 + tx * TN + j;
            if (gc < J) C[(size_t)gr * J + gc] = acc[i][j];
        }
    }
}

// ---------------- per-node attention scores: el/er ----------------
template <int H, int D>
__global__ void scores_k(const float* __restrict__ feat,
                         const float* __restrict__ al,
                         const float* __restrict__ ar,
                         float* __restrict__ el, float* __restrict__ er, int N) {
    int warp = (blockIdx.x * blockDim.x + threadIdx.x) >> 5;
    int lane = threadIdx.x & 31;
    if (warp >= N) return;
    const float* f = feat + (size_t)warp * (H * D);
    float accl[H], accr[H];
#pragma unroll
    for (int h = 0; h < H; h++) { accl[h] = 0.f; accr[h] = 0.f; }
    for (int i = lane; i < H * D; i += 32) {
        int h = i / D;
        float v = f[i];
        accl[h] += v * al[i];
        accr[h] += v * ar[i];
    }
#pragma unroll
    for (int h = 0; h < H; h++) {
        float l = accl[h], r = accr[h];
#pragma unroll
        for (int o = 16; o; o >>= 1) {
            l += __shfl_xor_sync(0xffffffffu, l, o);
            r += __shfl_xor_sync(0xffffffffu, r, o);
        }
        if (lane == 0) { el[warp * H + h] = l; er[warp * H + h] = r; }
    }
}

__global__ void fill_k(float* __restrict__ p, float v, int n) {
    int i = blockIdx.x * blockDim.x + threadIdx.x;
    if (i < n) p[i] = v;
}

// ---------------- edge pass 1: e = leaky_relu(el[src]+er[dst]); segment max ----------------
template <int H>
__global__ void edge_pass1(const int* __restrict__ src, const int* __restrict__ dst,
                           const float* __restrict__ el, const float* __restrict__ er,
                           float* __restrict__ e, float* __restrict__ emax, int E) {
    int idx = blockIdx.x * blockDim.x + threadIdx.x;
    if (idx >= E * H) return;
    int edge = idx / H, h = idx % H;
    int s = src[edge], d = dst[edge];
    float v = el[s * H + h] + er[d * H + h];
    v = (v > 0.f) ? v : 0.2f * v;
    e[idx] = v;
    atomicMaxF(&emax[d * H + h], v);
}

// ---------------- edge pass 2: ex = exp(e - emax[dst]); segment sum ----------------
template <int H>
__global__ void edge_pass2(const int* __restrict__ dst,
                           float* __restrict__ e, const float* __restrict__ emax,
                           float* __restrict__ den, int E) {
    int idx = blockIdx.x * blockDim.x + threadIdx.x;
    if (idx >= E * H) return;
    int edge = idx / H, h = idx % H;
    int d = dst[edge];
    float ex = __expf(e[idx] - emax[d * H + h]);
    e[idx] = ex;
    atomicAdd(&den[d * H + h], ex);
}

// ---------------- edge pass 3: out[dst] += feat[src] * alpha ----------------
template <int H, int D>
__global__ void edge_pass3(const int* __restrict__ src, const int* __restrict__ dst,
                           const float* __restrict__ feat, const float* __restrict__ ex,
                           const float* __restrict__ den, float* __restrict__ out, int E) {
    constexpr int V = (H * D) / 4;  // float4 lanes per edge
    int idx = blockIdx.x * blockDim.x + threadIdx.x;
    if (idx >= E * V) return;
    int edge = idx / V, t = idx % V;
    int h = (t * 4) / D;
    int s = src[edge], d = dst[edge];
    float a = ex[edge * H + h] / fmaxf(den[d * H + h], 1e-9f);
    float4 f = *(const float4*)(feat + (size_t)s * (H * D) + t * 4);
    float* o = out + (size_t)d * (H * D) + t * 4;
    atomicAdd(o + 0, f.x * a);
    atomicAdd(o + 1, f.y * a);
    atomicAdd(o + 2, f.z * a);
    atomicAdd(o + 3, f.w * a);
}

__global__ void elu_k(float* __restrict__ p, int n) {
    int i = blockIdx.x * blockDim.x + threadIdx.x;
    if (i < n) {
        float v = p[i];
        p[i] = (v > 0.f) ? v : (expm1f(v));
    }
}

// ---------------- one full GATConv layer ----------------
template <int H, int D>
static void run_layer(const float* in, int K, const float* W,
                      const float* al, const float* ar,
                      float* feat, float* outp, int act,
                      int N, int E, const int* src, const int* dst,
                      float* el, float* er, float* emax, float* den, float* ebuf) {
    const int J = H * D;
    dim3 grid((J + 63) / 64, (N + 63) / 64);
    sgemm<64, 64, 16, 4, 4><<<grid, 256>>>(in, W, feat, N, K, J);
    scores_k<H, D><<<(N * 32 + 255) / 256, 256>>>(feat, al, ar, el, er, N);
    fill_k<<<(N * H + 255) / 256, 256>>>(emax, -INFINITY, N * H);
    cudaMemsetAsync(den, 0, (size_t)N * H * sizeof(float));
    cudaMemsetAsync(outp, 0, (size_t)N * J * sizeof(float));
    edge_pass1<H><<<((long)E * H + 255) / 256, 256>>>(src, dst, el, er, ebuf, emax, E);
    edge_pass2<H><<<((long)E * H + 255) / 256, 256>>>(dst, ebuf, emax, den, E);
    const long tot = (long)E * (H * D / 4);
    edge_pass3<H, D><<<(tot + 255) / 256, 256>>>(src, dst, feat, ebuf, den, outp, E);
    if (act) elu_k<<<((long)N * J + 255) / 256, 256>>>(outp, N * J);
}

extern "C" void kernel_launch(void* const* d_in, const int* in_sizes, int n_in,
                              void* d_out, int out_size) {
    const float* x    = (const float*)d_in[0];
    const int*   src  = (const int*)d_in[1];
    const int*   dst  = (const int*)d_in[2];
    const float* W00  = (const float*)d_in[3];
    const float* a00l = (const float*)d_in[4];
    const float* a00r = (const float*)d_in[5];
    const float* W01  = (const float*)d_in[6];
    const float* a01l = (const float*)d_in[7];
    const float* a01r = (const float*)d_in[8];
    const float* W0f  = (const float*)d_in[9];
    const float* a0fl = (const float*)d_in[10];
    const float* a0fr = (const float*)d_in[11];
    const float* W10  = (const float*)d_in[12];
    const float* a10l = (const float*)d_in[13];
    const float* a10r = (const float*)d_in[14];
    const float* W1f  = (const float*)d_in[15];
    const float* a1fl = (const float*)d_in[16];
    const float* a1fr = (const float*)d_in[17];
    const float* W1o  = (const float*)d_in[18];
    const float* a1ol = (const float*)d_in[19];
    const float* a1or = (const float*)d_in[20];
    float* out = (float*)d_out;

    const int N = in_sizes[0] / 256;
    const int E = in_sizes[1];

    float *bufA, *bufB, *el, *er, *emax, *den, *ebuf;
    cudaGetSymbolAddress((void**)&bufA, g_bufA);
    cudaGetSymbolAddress((void**)&bufB, g_bufB);
    cudaGetSymbolAddress((void**)&el, g_el);
    cudaGetSymbolAddress((void**)&er, g_er);
    cudaGetSymbolAddress((void**)&emax, g_emax);
    cudaGetSymbolAddress((void**)&den, g_den);
    cudaGetSymbolAddress((void**)&ebuf, g_e);

    // ---- branch 0 ----
    // L00: x[N,256] -> feat[N,4,64] -> h(B) [N,256], elu
    run_layer<4, 64>(x, 256, W00, a00l, a00r, bufA, bufB, 1, N, E, src, dst, el, er, emax, den, ebuf);
    // L01: B[N,256] -> feat[N,1,64] -> h(B) [N,64], elu
    run_layer<1, 64>(bufB, 256, W01, a01l, a01r, bufA, bufB, 1, N, E, src, dst, el, er, emax, den, ebuf);
    // L0f: B[N,64] -> feat[N,1,40] -> y0 (d_out), no act
    run_layer<1, 40>(bufB, 64, W0f, a0fl, a0fr, bufA, out, 0, N, E, src, dst, el, er, emax, den, ebuf);

    // ---- branch 1 ----
    // L10: x[N,256] -> feat[N,4,64] -> h(B) [N,256], elu
    run_layer<4, 64>(x, 256, W10, a10l, a10r, bufA, bufB, 1, N, E, src, dst, el, er, emax, den, ebuf);
    // L1f: B[N,256] -> feat[N,1,64] -> emb(B) [N,64], no act
    run_layer<1, 64>(bufB, 256, W1f, a1fl, a1fr, bufA, bufB, 0, N, E, src, dst, el, er, emax, den, ebuf);
    // L1o: B[N,64] -> feat[N,1,40] -> y1 (d_out + N*C), elu
    run_layer<1, 40>(bufB, 64, W1o, a1ol, a1or, bufA, out + (size_t)N * CC, 1, N, E, src, dst, el, er, emax, den, ebuf);
}

// round 3
// speedup vs baseline: 2.5474x; 2.5474x over previous
#include <cuda_runtime.h>
#include <math.h>

#define NN 50000
#define EE 800000
#define CC 40

// ---------------- scratch (device globals; no allocations allowed) ----------------
__device__ float g_bufA[NN * 256];     // feat buffer
__device__ float g_bufB[NN * 256];     // layer output / next input
__device__ float g_el[NN * 4];
__device__ float g_er[NN * 4];
__device__ int   g_deg[NN];
__device__ int   g_rowptr[NN + 1];
__device__ int   g_wp[NN];
__device__ int   g_bsum[64];
__device__ int   g_csrc[EE];           // src ids grouped by dst (CSR payload)

// ================= CSR build =================
__global__ void zero_deg(int* deg, int N) {
    int i = blockIdx.x * blockDim.x + threadIdx.x;
    if (i < N) deg[i] = 0;
}
__global__ void hist_k(const int* __restrict__ dst, int* __restrict__ deg, int E) {
    int i = blockIdx.x * blockDim.x + threadIdx.x;
    if (i < E) atomicAdd(&deg[dst[i]], 1);
}
// tile-wise inclusive scan (1024/block) -> exclusive rowptr within tile + block sums
__global__ void scan_tiles(const int* __restrict__ deg, int* __restrict__ rowptr,
                           int* __restrict__ bsum, int N) {
    __shared__ int sh[1024];
    int i = blockIdx.x * 1024 + threadIdx.x;
    int v = (i < N) ? deg[i] : 0;
    sh[threadIdx.x] = v;
    __syncthreads();
    for (int o = 1; o < 1024; o <<= 1) {
        int t = (threadIdx.x >= o) ? sh[threadIdx.x - o] : 0;
        __syncthreads();
        sh[threadIdx.x] += t;
        __syncthreads();
    }
    if (i < N) rowptr[i] = sh[threadIdx.x] - v;  // exclusive
    if (threadIdx.x == 1023) bsum[blockIdx.x] = sh[1023];
}
__global__ void scan_bsum(int* bsum, int nb) {
    if (threadIdx.x == 0 && blockIdx.x == 0) {
        int acc = 0;
        for (int b = 0; b < nb; b++) { int t = bsum[b]; bsum[b] = acc; acc += t; }
    }
}
__global__ void add_off(int* __restrict__ rowptr, int* __restrict__ wp,
                        const int* __restrict__ bsum, int N, int E) {
    int i = blockIdx.x * blockDim.x + threadIdx.x;
    if (i < N) {
        int v = rowptr[i] + bsum[i >> 10];
        rowptr[i] = v;
        wp[i] = v;
    }
    if (i == 0) rowptr[N] = E;
}
__global__ void scatter_k(const int* __restrict__ src, const int* __restrict__ dst,
                          int* __restrict__ wp, int* __restrict__ csrc, int E) {
    int i = blockIdx.x * blockDim.x + threadIdx.x;
    if (i < E) {
        int pos = atomicAdd(&wp[dst[i]], 1);
        csrc[pos] = src[i];
    }
}

// ================= GEMM: C[M,J] = A[M,K] @ B[K,J] =================
// 256 threads; float4 global loads; As padded for conflict-free stores.
// Requires K % BK == 0, BK % 4 == 0, J % 4 == 0 (holds: K in {256,64}, J in {256,64,40}).
template <int BM, int BN, int BK, int TM, int TN>
__global__ __launch_bounds__(256) void sgemm(const float* __restrict__ A,
                                             const float* __restrict__ B,
                                             float* __restrict__ C,
                                             int M, int K, int J) {
    static_assert((BM / TM) * (BN / TN) == 256, "thread shape");
    __shared__ float As[BK][BM + 1];
    __shared__ float Bs[BK][BN];
    int tid = threadIdx.x;
    int row0 = blockIdx.y * BM;
    int col0 = blockIdx.x * BN;
    int tx = tid % (BN / TN);
    int ty = tid / (BN / TN);

    float acc[TM][TN];
#pragma unroll
    for (int i = 0; i < TM; i++)
#pragma unroll
        for (int j = 0; j < TN; j++) acc[i][j] = 0.f;

    for (int k0 = 0; k0 < K; k0 += BK) {
        // A tile: float4 along K, store transposed
#pragma unroll
        for (int i = tid; i < BM * BK / 4; i += 256) {
            int r = i / (BK / 4);
            int kc = (i % (BK / 4)) * 4;
            int gr = row0 + r;
            float4 v = make_float4(0.f, 0.f, 0.f, 0.f);
            if (gr < M) v = *(const float4*)&A[(size_t)gr * K + (k0 + kc)];
            As[kc + 0][r] = v.x;
            As[kc + 1][r] = v.y;
            As[kc + 2][r] = v.z;
            As[kc + 3][r] = v.w;
        }
        // B tile: float4 along J
#pragma unroll
        for (int i = tid; i < BK * BN / 4; i += 256) {
            int r = i / (BN / 4);
            int c = (i % (BN / 4)) * 4;
            int gc = col0 + c;
            float4 v = make_float4(0.f, 0.f, 0.f, 0.f);
            if (gc + 3 < J) v = *(const float4*)&B[(size_t)(k0 + r) * J + gc];
            *(float4*)&Bs[r][c] = v;
        }
        __syncthreads();
#pragma unroll
        for (int kk = 0; kk < BK; kk++) {
            float a[TM], b[TN];
#pragma unroll
            for (int i = 0; i < TM; i++) a[i] = As[kk][ty * TM + i];
#pragma unroll
            for (int j = 0; j < TN; j++) b[j] = Bs[kk][tx * TN + j];
#pragma unroll
            for (int i = 0; i < TM; i++)
#pragma unroll
                for (int j = 0; j < TN; j++) acc[i][j] += a[i] * b[j];
        }
        __syncthreads();
    }
#pragma unroll
    for (int i = 0; i < TM; i++) {
        int gr = row0 + ty * TM + i;
        if (gr >= M) continue;
#pragma unroll
        for (int j = 0; j < TN; j++) {
            int gc = col0 + tx * TN + j;
            if (gc < J) C[(size_t)gr * J + gc] = acc[i][j];
        }
    }
}

// ================= per-node attention scores: el/er =================
template <int H, int D>
__global__ void scores_k(const float* __restrict__ feat,
                         const float* __restrict__ al,
                         const float* __restrict__ ar,
                         float* __restrict__ el, float* __restrict__ er, int N) {
    int warp = (blockIdx.x * blockDim.x + threadIdx.x) >> 5;
    int lane = threadIdx.x & 31;
    if (warp >= N) return;
    const float* f = feat + (size_t)warp * (H * D);
    float accl[H], accr[H];
#pragma unroll
    for (int h = 0; h < H; h++) { accl[h] = 0.f; accr[h] = 0.f; }
    for (int i = lane; i < H * D; i += 32) {
        int h = i / D;
        float v = f[i];
        accl[h] += v * al[i];
        accr[h] += v * ar[i];
    }
#pragma unroll
    for (int h = 0; h < H; h++) {
        float l = accl[h], r = accr[h];
#pragma unroll
        for (int o = 16; o; o >>= 1) {
            l += __shfl_xor_sync(0xffffffffu, l, o);
            r += __shfl_xor_sync(0xffffffffu, r, o);
        }
        if (lane == 0) { el[warp * H + h] = l; er[warp * H + h] = r; }
    }
}

// ================= fused softmax + aggregate (CSR, one warp per dst node) ===========
template <int H, int D, int ACT>
__global__ __launch_bounds__(256) void agg_k(const int* __restrict__ rowptr,
                                             const int* __restrict__ csrc,
                                             const float* __restrict__ el,
                                             const float* __restrict__ er,
                                             const float* __restrict__ feat,
                                             float* __restrict__ out, int N) {
    constexpr int HD = H * D;
    constexpr int PC = (HD + 31) / 32;
    int warp = (blockIdx.x * blockDim.x + threadIdx.x) >> 5;
    int lane = threadIdx.x & 31;
    if (warp >= N) return;
    int beg = rowptr[warp];
    int end = rowptr[warp + 1];

    float erh[H];
    if (H == 4) {
        float4 t = ((const float4*)er)[warp];
        erh[0] = t.x; erh[1] = t.y; erh[2] = t.z; erh[3] = t.w;
    } else {
        erh[0] = er[warp];
    }

    // pass A: per-head max of leaky(el[src]+er[dst])
    float m[H];
#pragma unroll
    for (int h = 0; h < H; h++) m[h] = -1e30f;
    for (int j = beg + lane; j < end; j += 32) {
        int s = csrc[j];
        float eh[H];
        if (H == 4) {
            float4 t = ((const float4*)el)[s];
            eh[0] = t.x; eh[1] = t.y; eh[2] = t.z; eh[3] = t.w;
        } else eh[0] = el[s];
#pragma unroll
        for (int h = 0; h < H; h++) {
            float v = eh[h] + erh[h];
            v = (v > 0.f) ? v : 0.2f * v;
            m[h] = fmaxf(m[h], v);
        }
    }
#pragma unroll
    for (int h = 0; h < H; h++)
#pragma unroll
        for (int o = 16; o; o >>= 1) m[h] = fmaxf(m[h], __shfl_xor_sync(0xffffffffu, m[h], o));

    // pass B: denominator
    float den[H];
#pragma unroll
    for (int h = 0; h < H; h++) den[h] = 0.f;
    for (int j = beg + lane; j < end; j += 32) {
        int s = csrc[j];
        float eh[H];
        if (H == 4) {
            float4 t = ((const float4*)el)[s];
            eh[0] = t.x; eh[1] = t.y; eh[2] = t.z; eh[3] = t.w;
        } else eh[0] = el[s];
#pragma unroll
        for (int h = 0; h < H; h++) {
            float v = eh[h] + erh[h];
            v = (v > 0.f) ? v : 0.2f * v;
            den[h] += __expf(v - m[h]);
        }
    }
    float inv[H];
#pragma unroll
    for (int h = 0; h < H; h++) {
#pragma unroll
        for (int o = 16; o; o >>= 1) den[h] += __shfl_xor_sync(0xffffffffu, den[h], o);
        inv[h] = 1.f / fmaxf(den[h], 1e-9f);
    }

    // lane-scalar selections for pass C (lane h computes alpha_h)
    float m_s = m[0], inv_s = inv[0], er_s = erh[0];
#pragma unroll
    for (int h = 1; h < H; h++)
        if (lane == h) { m_s = m[h]; inv_s = inv[h]; er_s = erh[h]; }

    // pass C: weighted gather
    float acc[PC];
#pragma unroll
    for (int k = 0; k < PC; k++) acc[k] = 0.f;
    for (int j = beg; j < end; j++) {
        int s = csrc[j];  // uniform within warp
        float a = 0.f;
        if (lane < H) {
            float v = el[s * H + lane] + er_s;
            v = (v > 0.f) ? v : 0.2f * v;
            a = __expf(v - m_s) * inv_s;
        }
        float alpha[H];
#pragma unroll
        for (int h = 0; h < H; h++) alpha[h] = __shfl_sync(0xffffffffu, a, h);
        const float* fr = feat + (size_t)s * HD;
#pragma unroll
        for (int k = 0; k < PC; k++) {
            const int hk = (k * 32) / D;   // head index (constant per k for our shapes)
            int c = k * 32 + lane;
            if ((HD % 32 == 0) || c < HD) acc[k] += fr[c] * alpha[hk];
        }
    }
#pragma unroll
    for (int k = 0; k < PC; k++) {
        int c = k * 32 + lane;
        if ((HD % 32 == 0) || c < HD) {
            float v = acc[k];
            if (ACT) v = (v > 0.f) ? v : expm1f(v);
            out[(size_t)warp * HD + c] = v;
        }
    }
}

// ================= one full GATConv layer =================
template <int H, int D, int ACT>
static void run_layer(const float* in, int K, const float* W,
                      const float* al, const float* ar,
                      float* feat, float* outp,
                      int N, const int* rowptr, const int* csrc,
                      float* el, float* er) {
    const int J = H * D;
    if (J == 256) {
        dim3 grid((J + 127) / 128, (N + 127) / 128);
        sgemm<128, 128, 16, 8, 8><<<grid, 256>>>(in, W, feat, N, K, J);
    } else if (J == 64) {
        dim3 grid(1, (N + 127) / 128);
        sgemm<128, 64, 16, 8, 4><<<grid, 256>>>(in, W, feat, N, K, J);
    } else {
        dim3 grid((J + 63) / 64, (N + 63) / 64);
        sgemm<64, 64, 16, 4, 4><<<grid, 256>>>(in, W, feat, N, K, J);
    }
    scores_k<H, D><<<(N * 32 + 255) / 256, 256>>>(feat, al, ar, el, er, N);
    agg_k<H, D, ACT><<<(N * 32 + 255) / 256, 256>>>(rowptr, csrc, el, er, feat, outp, N);
}

extern "C" void kernel_launch(void* const* d_in, const int* in_sizes, int n_in,
                              void* d_out, int out_size) {
    const float* x    = (const float*)d_in[0];
    const int*   src  = (const int*)d_in[1];
    const int*   dst  = (const int*)d_in[2];
    const float* W00  = (const float*)d_in[3];
    const float* a00l = (const float*)d_in[4];
    const float* a00r = (const float*)d_in[5];
    const float* W01  = (const float*)d_in[6];
    const float* a01l = (const float*)d_in[7];
    const float* a01r = (const float*)d_in[8];
    const float* W0f  = (const float*)d_in[9];
    const float* a0fl = (const float*)d_in[10];
    const float* a0fr = (const float*)d_in[11];
    const float* W10  = (const float*)d_in[12];
    const float* a10l = (const float*)d_in[13];
    const float* a10r = (const float*)d_in[14];
    const float* W1f  = (const float*)d_in[15];
    const float* a1fl = (const float*)d_in[16];
    const float* a1fr = (const float*)d_in[17];
    const float* W1o  = (const float*)d_in[18];
    const float* a1ol = (const float*)d_in[19];
    const float* a1or = (const float*)d_in[20];
    float* out = (float*)d_out;

    const int N = in_sizes[0] / 256;
    const int E = in_sizes[1];

    float *bufA, *bufB, *el, *er;
    int *deg, *rowptr, *wp, *bsum, *csrc;
    cudaGetSymbolAddress((void**)&bufA, g_bufA);
    cudaGetSymbolAddress((void**)&bufB, g_bufB);
    cudaGetSymbolAddress((void**)&el, g_el);
    cudaGetSymbolAddress((void**)&er, g_er);
    cudaGetSymbolAddress((void**)&deg, g_deg);
    cudaGetSymbolAddress((void**)&rowptr, g_rowptr);
    cudaGetSymbolAddress((void**)&wp, g_wp);
    cudaGetSymbolAddress((void**)&bsum, g_bsum);
    cudaGetSymbolAddress((void**)&csrc, g_csrc);

    // ---- build dst-CSR once (shared by all 6 layers) ----
    zero_deg<<<(N + 255) / 256, 256>>>(deg, N);
    hist_k<<<(E + 255) / 256, 256>>>(dst, deg, E);
    int ntiles = (N + 1023) / 1024;
    scan_tiles<<<ntiles, 1024>>>(deg, rowptr, bsum, N);
    scan_bsum<<<1, 32>>>(bsum, ntiles);
    add_off<<<(N + 255) / 256, 256>>>(rowptr, wp, bsum, N, E);
    scatter_k<<<(E + 255) / 256, 256>>>(src, dst, wp, csrc, E);

    // ---- branch 0 ----
    run_layer<4, 64, 1>(x,    256, W00, a00l, a00r, bufA, bufB, N, rowptr, csrc, el, er);
    run_layer<1, 64, 1>(bufB, 256, W01, a01l, a01r, bufA, bufB, N, rowptr, csrc, el, er);
    run_layer<1, 40, 0>(bufB, 64,  W0f, a0fl, a0fr, bufA, out,  N, rowptr, csrc, el, er);

    // ---- branch 1 ----
    run_layer<4, 64, 1>(x,    256, W10, a10l, a10r, bufA, bufB, N, rowptr, csrc, el, er);
    run_layer<1, 64, 0>(bufB, 256, W1f, a1fl, a1fr, bufA, bufB, N, rowptr, csrc, el, er);
    run_layer<1, 40, 1>(bufB, 64,  W1o, a1ol, a1or, bufA, out + (size_t)N * CC, N, rowptr, csrc, el, er);
}

// round 7
// speedup vs baseline: 3.4197x; 1.3424x over previous
#include <cuda_runtime.h>
#include <cuda_bf16.h>
#include <math.h>
#include <stdint.h>

#define NN 50000
#define EE 800000
#define CC 40

// ---------------- scratch (device globals; no allocations allowed) ----------------
__device__ __align__(16) float g_feat[NN * 256];           // GEMM output (fp32)
__device__ float g_el[NN * 4];
__device__ float g_er[NN * 4];
__device__ __align__(16) __nv_bfloat16 g_xhi[NN * 256];    // x split (built once)
__device__ __align__(16) __nv_bfloat16 g_xlo[NN * 256];
__device__ __align__(16) __nv_bfloat16 g_hhi[NN * 256];    // intermediate split
__device__ __align__(16) __nv_bfloat16 g_hlo[NN * 256];
__device__ __align__(16) __nv_bfloat16 g_whi[256 * 256];   // W^T split (padded)
__device__ __align__(16) __nv_bfloat16 g_wlo[256 * 256];
__device__ int   g_deg[NN];
__device__ int   g_rowptr[NN + 1];
__device__ int   g_wp[NN];
__device__ int   g_bsum[64];
__device__ int   g_csrc[EE];

// ================= CSR build =================
__global__ void zero_deg(int* deg, int N) {
    int i = blockIdx.x * blockDim.x + threadIdx.x;
    if (i < N) deg[i] = 0;
}
__global__ void hist_k(const int* __restrict__ dst, int* __restrict__ deg, int E) {
    int i = blockIdx.x * blockDim.x + threadIdx.x;
    if (i < E) atomicAdd(&deg[dst[i]], 1);
}
__global__ void scan_tiles(const int* __restrict__ deg, int* __restrict__ rowptr,
                           int* __restrict__ bsum, int N) {
    __shared__ int sh[1024];
    int i = blockIdx.x * 1024 + threadIdx.x;
    int v = (i < N) ? deg[i] : 0;
    sh[threadIdx.x] = v;
    __syncthreads();
    for (int o = 1; o < 1024; o <<= 1) {
        int t = (threadIdx.x >= o) ? sh[threadIdx.x - o] : 0;
        __syncthreads();
        sh[threadIdx.x] += t;
        __syncthreads();
    }
    if (i < N) rowptr[i] = sh[threadIdx.x] - v;
    if (threadIdx.x == 1023) bsum[blockIdx.x] = sh[1023];
}
__global__ void scan_bsum(int* bsum, int nb) {
    if (threadIdx.x == 0 && blockIdx.x == 0) {
        int acc = 0;
        for (int b = 0; b < nb; b++) { int t = bsum[b]; bsum[b] = acc; acc += t; }
    }
}
__global__ void add_off(int* __restrict__ rowptr, int* __restrict__ wp,
                        const int* __restrict__ bsum, int N, int E) {
    int i = blockIdx.x * blockDim.x + threadIdx.x;
    if (i < N) {
        int v = rowptr[i] + bsum[i >> 10];
        rowptr[i] = v;
        wp[i] = v;
    }
    if (i == 0) rowptr[N] = E;
}
__global__ void scatter_k(const int* __restrict__ src, const int* __restrict__ dst,
                          int* __restrict__ wp, int* __restrict__ csrc, int E) {
    int i = blockIdx.x * blockDim.x + threadIdx.x;
    if (i < E) {
        int pos = atomicAdd(&wp[dst[i]], 1);
        csrc[pos] = src[i];
    }
}

// ================= split / W-prep =================
__global__ void split_k(const float* __restrict__ v, __nv_bfloat16* __restrict__ hi,
                        __nv_bfloat16* __restrict__ lo, int n) {
    int i = blockIdx.x * blockDim.x + threadIdx.x;
    if (i < n) {
        float f = v[i];
        __nv_bfloat16 h = __float2bfloat16(f);
        hi[i] = h;
        lo[i] = __float2bfloat16(f - __bfloat162float(h));
    }
}
// W[k*J+j] -> Wt[j*K+k], zero-padded to J64 rows
__global__ void prepw_k(const float* __restrict__ W, __nv_bfloat16* __restrict__ hi,
                        __nv_bfloat16* __restrict__ lo, int K, int J, int J64) {
    int i = blockIdx.x * blockDim.x + threadIdx.x;
    if (i < K * J64) {
        int j = i / K, k = i % K;
        float f = (j < J) ? W[k * J + j] : 0.f;
        __nv_bfloat16 h = __float2bfloat16(f);
        hi[i] = h;
        lo[i] = __float2bfloat16(f - __bfloat162float(h));
    }
}

// ================= mma.sync bf16 GEMM: C[M,J] = A[M,K] @ W[K,J], split x3 =================
// A (hi/lo): [M,K] bf16 row-major. B (hi/lo): W^T [J64,K] bf16 (row j = output col).
// Block: 256 thr = 8 warps (4 along M x 2 along N); block tile 128x64; warp tile 32x32.
#define MMA_BF16(d, a, b)                                                          \
    asm volatile(                                                                  \
        "mma.sync.aligned.m16n8k16.row.col.f32.bf16.bf16.f32 "                     \
        "{%0,%1,%2,%3},{%4,%5,%6,%7},{%8,%9},{%0,%1,%2,%3};"                       \
        : "+f"((d)[0]), "+f"((d)[1]), "+f"((d)[2]), "+f"((d)[3])                   \
        : "r"((a)[0]), "r"((a)[1]), "r"((a)[2]), "r"((a)[3]), "r"((b)[0]), "r"((b)[1]))

template <int K, int J>
__global__ __launch_bounds__(256) void gemm_mma(
    const __nv_bfloat16* __restrict__ Ahi, const __nv_bfloat16* __restrict__ Alo,
    const __nv_bfloat16* __restrict__ Bhi, const __nv_bfloat16* __restrict__ Blo,
    float* __restrict__ C, int M) {
    constexpr int BK = 32, STR = BK + 8;
    __shared__ __nv_bfloat16 sAh[128 * STR], sAl[128 * STR];
    __shared__ __nv_bfloat16 sBh[64 * STR], sBl[64 * STR];
    const int tid = threadIdx.x;
    const int wid = tid >> 5, lane = tid & 31;
    const int g = lane >> 2, t = lane & 3;
    const int wm = wid & 3, wn = wid >> 2;
    const int row0 = blockIdx.y * 128, col0 = blockIdx.x * 64;

    float acc[2][4][4];
#pragma unroll
    for (int am = 0; am < 2; am++)
#pragma unroll
        for (int an = 0; an < 4; an++)
#pragma unroll
            for (int q = 0; q < 4; q++) acc[am][an][q] = 0.f;

    for (int kb = 0; kb < K; kb += BK) {
        // stage A tile [128 x BK] hi/lo (uint4 = 8 bf16)
#pragma unroll
        for (int i = tid; i < 128 * BK / 8; i += 256) {
            int r = i >> 2, cb = (i & 3) * 8;
            int gr = min(row0 + r, M - 1);
            *(uint4*)&sAh[r * STR + cb] = *(const uint4*)&Ahi[(size_t)gr * K + kb + cb];
            *(uint4*)&sAl[r * STR + cb] = *(const uint4*)&Alo[(size_t)gr * K + kb + cb];
        }
        // stage B tile [64 x BK] hi/lo
#pragma unroll
        for (int i = tid; i < 64 * BK / 8; i += 256) {
            int r = i >> 2, cb = (i & 3) * 8;
            *(uint4*)&sBh[r * STR + cb] = *(const uint4*)&Bhi[(size_t)(col0 + r) * K + kb + cb];
            *(uint4*)&sBl[r * STR + cb] = *(const uint4*)&Blo[(size_t)(col0 + r) * K + kb + cb];
        }
        __syncthreads();
#pragma unroll
        for (int ks = 0; ks < BK / 16; ks++) {
            const int k0 = ks * 16;
            uint32_t ah[2][4], al_[2][4], bh[4][2], bl[4][2];
#pragma unroll
            for (int am = 0; am < 2; am++) {
                int rb = wm * 32 + am * 16;
                ah[am][0] = *(const uint32_t*)&sAh[(rb + g) * STR + k0 + 2 * t];
                ah[am][1] = *(const uint32_t*)&sAh[(rb + g + 8) * STR + k0 + 2 * t];
                ah[am][2] = *(const uint32_t*)&sAh[(rb + g) * STR + k0 + 2 * t + 8];
                ah[am][3] = *(const uint32_t*)&sAh[(rb + g + 8) * STR + k0 + 2 * t + 8];
                al_[am][0] = *(const uint32_t*)&sAl[(rb + g) * STR + k0 + 2 * t];
                al_[am][1] = *(const uint32_t*)&sAl[(rb + g + 8) * STR + k0 + 2 * t];
                al_[am][2] = *(const uint32_t*)&sAl[(rb + g) * STR + k0 + 2 * t + 8];
                al_[am][3] = *(const uint32_t*)&sAl[(rb + g + 8) * STR + k0 + 2 * t + 8];
            }
#pragma unroll
            for (int an = 0; an < 4; an++) {
                int c = wn * 32 + an * 8 + g;
                bh[an][0] = *(const uint32_t*)&sBh[c * STR + k0 + 2 * t];
                bh[an][1] = *(const uint32_t*)&sBh[c * STR + k0 + 2 * t + 8];
                bl[an][0] = *(const uint32_t*)&sBl[c * STR + k0 + 2 * t];
                bl[an][1] = *(const uint32_t*)&sBl[c * STR + k0 + 2 * t + 8];
            }
#pragma unroll
            for (int am = 0; am < 2; am++)
#pragma unroll
                for (int an = 0; an < 4; an++) {
                    MMA_BF16(acc[am][an], ah[am], bh[an]);
                    MMA_BF16(acc[am][an], ah[am], bl[an]);
                    MMA_BF16(acc[am][an], al_[am], bh[an]);
                }
        }
        __syncthreads();
    }
    // store C (fp32)
#pragma unroll
    for (int am = 0; am < 2; am++) {
        int r0 = row0 + wm * 32 + am * 16 + g;
#pragma unroll
        for (int an = 0; an < 4; an++) {
            int c = col0 + wn * 32 + an * 8 + 2 * t;
            if (c < J) {
                if (r0 < M)
                    *(float2*)&C[(size_t)r0 * J + c] = make_float2(acc[am][an][0], acc[am][an][1]);
                if (r0 + 8 < M)
                    *(float2*)&C[(size_t)(r0 + 8) * J + c] = make_float2(acc[am][an][2], acc[am][an][3]);
            }
        }
    }
}

// ================= per-node attention scores: el/er =================
template <int H, int D>
__global__ void scores_k(const float* __restrict__ feat,
                         const float* __restrict__ al,
                         const float* __restrict__ ar,
                         float* __restrict__ el, float* __restrict__ er, int N) {
    int warp = (blockIdx.x * blockDim.x + threadIdx.x) >> 5;
    int lane = threadIdx.x & 31;
    if (warp >= N) return;
    const float* f = feat + (size_t)warp * (H * D);
    float accl[H], accr[H];
#pragma unroll
    for (int h = 0; h < H; h++) { accl[h] = 0.f; accr[h] = 0.f; }
    for (int i = lane; i < H * D; i += 32) {
        int h = i / D;
        float v = f[i];
        accl[h] += v * al[i];
        accr[h] += v * ar[i];
    }
#pragma unroll
    for (int h = 0; h < H; h++) {
        float l = accl[h], r = accr[h];
#pragma unroll
        for (int o = 16; o; o >>= 1) {
            l += __shfl_xor_sync(0xffffffffu, l, o);
            r += __shfl_xor_sync(0xffffffffu, r, o);
        }
        if (lane == 0) { el[warp * H + h] = l; er[warp * H + h] = r; }
    }
}

// ================= fused softmax + aggregate (CSR, one warp per dst node) ===========
// WM==0: write fp32 to out. WM==1: write split bf16 hi/lo (next layer's GEMM input).
template <int H, int D, int ACT, int WM>
__global__ __launch_bounds__(256) void agg_k(const int* __restrict__ rowptr,
                                             const int* __restrict__ csrc,
                                             const float* __restrict__ el,
                                             const float* __restrict__ er,
                                             const float* __restrict__ feat,
                                             float* __restrict__ out,
                                             __nv_bfloat16* __restrict__ ohi,
                                             __nv_bfloat16* __restrict__ olo, int N) {
    constexpr int HD = H * D;
    constexpr int PC = (HD + 31) / 32;
    int warp = (blockIdx.x * blockDim.x + threadIdx.x) >> 5;
    int lane = threadIdx.x & 31;
    if (warp >= N) return;
    int beg = rowptr[warp];
    int end = rowptr[warp + 1];

    float erh[H];
    if (H == 4) {
        float4 t = ((const float4*)er)[warp];
        erh[0] = t.x; erh[1] = t.y; erh[2] = t.z; erh[3] = t.w;
    } else {
        erh[0] = er[warp];
    }

    float m[H];
#pragma unroll
    for (int h = 0; h < H; h++) m[h] = -1e30f;
    for (int j = beg + lane; j < end; j += 32) {
        int s = csrc[j];
        float eh[H];
        if (H == 4) {
            float4 t = ((const float4*)el)[s];
            eh[0] = t.x; eh[1] = t.y; eh[2] = t.z; eh[3] = t.w;
        } else eh[0] = el[s];
#pragma unroll
        for (int h = 0; h < H; h++) {
            float v = eh[h] + erh[h];
            v = (v > 0.f) ? v : 0.2f * v;
            m[h] = fmaxf(m[h], v);
        }
    }
#pragma unroll
    for (int h = 0; h < H; h++)
#pragma unroll
        for (int o = 16; o; o >>= 1) m[h] = fmaxf(m[h], __shfl_xor_sync(0xffffffffu, m[h], o));

    float den[H];
#pragma unroll
    for (int h = 0; h < H; h++) den[h] = 0.f;
    for (int j = beg + lane; j < end; j += 32) {
        int s = csrc[j];
        float eh[H];
        if (H == 4) {
            float4 t = ((const float4*)el)[s];
            eh[0] = t.x; eh[1] = t.y; eh[2] = t.z; eh[3] = t.w;
        } else eh[0] = el[s];
#pragma unroll
        for (int h = 0; h < H; h++) {
            float v = eh[h] + erh[h];
            v = (v > 0.f) ? v : 0.2f * v;
            den[h] += __expf(v - m[h]);
        }
    }
    float inv[H];
#pragma unroll
    for (int h = 0; h < H; h++) {
#pragma unroll
        for (int o = 16; o; o >>= 1) den[h] += __shfl_xor_sync(0xffffffffu, den[h], o);
        inv[h] = 1.f / fmaxf(den[h], 1e-9f);
    }

    float m_s = m[0], inv_s = inv[0], er_s = erh[0];
#pragma unroll
    for (int h = 1; h < H; h++)
        if (lane == h) { m_s = m[h]; inv_s = inv[h]; er_s = erh[h]; }

    float acc[PC];
#pragma unroll
    for (int k = 0; k < PC; k++) acc[k] = 0.f;
    for (int j = beg; j < end; j++) {
        int s = csrc[j];
        float a = 0.f;
        if (lane < H) {
            float v = el[s * H + lane] + er_s;
            v = (v > 0.f) ? v : 0.2f * v;
            a = __expf(v - m_s) * inv_s;
        }
        float alpha[H];
#pragma unroll
        for (int h = 0; h < H; h++) alpha[h] = __shfl_sync(0xffffffffu, a, h);
        const float* fr = feat + (size_t)s * HD;
#pragma unroll
        for (int k = 0; k < PC; k++) {
            const int hk = (k * 32) / D;
            int c = k * 32 + lane;
            if ((HD % 32 == 0) || c < HD) acc[k] += fr[c] * alpha[hk];
        }
    }
#pragma unroll
    for (int k = 0; k < PC; k++) {
        int c = k * 32 + lane;
        if ((HD % 32 == 0) || c < HD) {
            float v = acc[k];
            if (ACT) v = (v > 0.f) ? v : expm1f(v);
            size_t idx = (size_t)warp * HD + c;
            if (WM == 0) {
                out[idx] = v;
            } else {
                __nv_bfloat16 hbf = __float2bfloat16(v);
                ohi[idx] = hbf;
                olo[idx] = __float2bfloat16(v - __bfloat162float(hbf));
            }
        }
    }
}

// ================= one full GATConv layer =================
template <int K, int H, int D, int ACT, int WM>
static void run_layer(const __nv_bfloat16* Ahi, const __nv_bfloat16* Alo,
                      const float* W, const float* al, const float* ar,
                      float* feat, float* outf, __nv_bfloat16* ohi, __nv_bfloat16* olo,
                      int N, const int* rowptr, const int* csrc, float* el, float* er,
                      __nv_bfloat16* whi, __nv_bfloat16* wlo) {
    constexpr int J = H * D;
    constexpr int J64 = (J + 63) / 64 * 64;
    prepw_k<<<(K * J64 + 255) / 256, 256>>>(W, whi, wlo, K, J, J64);
    dim3 grid(J64 / 64, (N + 127) / 128);
    gemm_mma<K, J><<<grid, 256>>>(Ahi, Alo, whi, wlo, feat, N);
    scores_k<H, D><<<(N * 32 + 255) / 256, 256>>>(feat, al, ar, el, er, N);
    agg_k<H, D, ACT, WM><<<(N * 32 + 255) / 256, 256>>>(rowptr, csrc, el, er, feat,
                                                        outf, ohi, olo, N);
}

extern "C" void kernel_launch(void* const* d_in, const int* in_sizes, int n_in,
                              void* d_out, int out_size) {
    const float* x    = (const float*)d_in[0];
    const int*   src  = (const int*)d_in[1];
    const int*   dst  = (const int*)d_in[2];
    const float* W00  = (const float*)d_in[3];
    const float* a00l = (const float*)d_in[4];
    const float* a00r = (const float*)d_in[5];
    const float* W01  = (const float*)d_in[6];
    const float* a01l = (const float*)d_in[7];
    const float* a01r = (const float*)d_in[8];
    const float* W0f  = (const float*)d_in[9];
    const float* a0fl = (const float*)d_in[10];
    const float* a0fr = (const float*)d_in[11];
    const float* W10  = (const float*)d_in[12];
    const float* a10l = (const float*)d_in[13];
    const float* a10r = (const float*)d_in[14];
    const float* W1f  = (const float*)d_in[15];
    const float* a1fl = (const float*)d_in[16];
    const float* a1fr = (const float*)d_in[17];
    const float* W1o  = (const float*)d_in[18];
    const float* a1ol = (const float*)d_in[19];
    const float* a1or = (const float*)d_in[20];
    float* out = (float*)d_out;

    const int N = in_sizes[0] / 256;
    const int E = in_sizes[1];

    float *feat, *el, *er;
    __nv_bfloat16 *xhi, *xlo, *hhi, *hlo, *whi, *wlo;
    int *deg, *rowptr, *wp, *bsum, *csrc;
    cudaGetSymbolAddress((void**)&feat, g_feat);
    cudaGetSymbolAddress((void**)&el, g_el);
    cudaGetSymbolAddress((void**)&er, g_er);
    cudaGetSymbolAddress((void**)&xhi, g_xhi);
    cudaGetSymbolAddress((void**)&xlo, g_xlo);
    cudaGetSymbolAddress((void**)&hhi, g_hhi);
    cudaGetSymbolAddress((void**)&hlo, g_hlo);
    cudaGetSymbolAddress((void**)&whi, g_whi);
    cudaGetSymbolAddress((void**)&wlo, g_wlo);
    cudaGetSymbolAddress((void**)&deg, g_deg);
    cudaGetSymbolAddress((void**)&rowptr, g_rowptr);
    cudaGetSymbolAddress((void**)&wp, g_wp);
    cudaGetSymbolAddress((void**)&bsum, g_bsum);
    cudaGetSymbolAddress((void**)&csrc, g_csrc);

    // ---- x split + dst-CSR build (shared by all layers) ----
    split_k<<<((long)N * 256 + 255) / 256, 256>>>(x, xhi, xlo, N * 256);
    zero_deg<<<(N + 255) / 256, 256>>>(deg, N);
    hist_k<<<(E + 255) / 256, 256>>>(dst, deg, E);
    int ntiles = (N + 1023) / 1024;
    scan_tiles<<<ntiles, 1024>>>(deg, rowptr, bsum, N);
    scan_bsum<<<1, 32>>>(bsum, ntiles);
    add_off<<<(N + 255) / 256, 256>>>(rowptr, wp, bsum, N, E);
    scatter_k<<<(E + 255) / 256, 256>>>(src, dst, wp, csrc, E);

    // ---- branch 0 ----
    run_layer<256, 4, 64, 1, 1>(xhi, xlo, W00, a00l, a00r, feat, nullptr, hhi, hlo,
                                N, rowptr, csrc, el, er, whi, wlo);
    run_layer<256, 1, 64, 1, 1>(hhi, hlo, W01, a01l, a01r, feat, nullptr, hhi, hlo,
                                N, rowptr, csrc, el, er, whi, wlo);
    run_layer<64, 1, 40, 0, 0>(hhi, hlo, W0f, a0fl, a0fr, feat, out, nullptr, nullptr,
                               N, rowptr, csrc, el, er, whi, wlo);

    // ---- branch 1 ----
    run_layer<256, 4, 64, 1, 1>(xhi, xlo, W10, a10l, a10r, feat, nullptr, hhi, hlo,
                                N, rowptr, csrc, el, er, whi, wlo);
    run_layer<256, 1, 64, 0, 1>(hhi, hlo, W1f, a1fl, a1fr, feat, nullptr, hhi, hlo,
                                N, rowptr, csrc, el, er, whi, wlo);
    run_layer<64, 1, 40, 1, 0>(hhi, hlo, W1o, a1ol, a1or, feat, out + (size_t)N * CC,
                               nullptr, nullptr, N, rowptr, csrc, el, er, whi, wlo);
}

// round 9
// speedup vs baseline: 3.8161x; 1.1159x over previous
#include <cuda_runtime.h>
#include <cuda_bf16.h>
#include <math.h>
#include <stdint.h>

#define NN 50000
#define EE 800000
#define CC 40

// ---------------- scratch (device globals; no allocations allowed) ----------------
__device__ __align__(16) float g_feat[NN * 256];           // GEMM output (fp32)
__device__ __align__(16) float g_el[NN * 4];
__device__ __align__(16) float g_er[NN * 4];
__device__ __align__(16) __nv_bfloat16 g_xhi[NN * 256];    // x split (built once)
__device__ __align__(16) __nv_bfloat16 g_xlo[NN * 256];
__device__ __align__(16) __nv_bfloat16 g_hhi[NN * 256];    // intermediate split
__device__ __align__(16) __nv_bfloat16 g_hlo[NN * 256];
__device__ __align__(16) __nv_bfloat16 g_whi[256 * 256];   // W^T split (padded)
__device__ __align__(16) __nv_bfloat16 g_wlo[256 * 256];
__device__ int   g_deg[NN];
__device__ int   g_rowptr[NN + 1];
__device__ int   g_wp[NN];
__device__ int   g_bsum[64];
__device__ int   g_csrc[EE];

// ================= CSR build =================
__global__ void zero_deg(int* deg, int N) {
    int i = blockIdx.x * blockDim.x + threadIdx.x;
    if (i < N) deg[i] = 0;
}
__global__ void hist_k(const int* __restrict__ dst, int* __restrict__ deg, int E) {
    int i = blockIdx.x * blockDim.x + threadIdx.x;
    if (i < E) atomicAdd(&deg[dst[i]], 1);
}
__global__ void scan_tiles(const int* __restrict__ deg, int* __restrict__ rowptr,
                           int* __restrict__ bsum, int N) {
    __shared__ int sh[1024];
    int i = blockIdx.x * 1024 + threadIdx.x;
    int v = (i < N) ? deg[i] : 0;
    sh[threadIdx.x] = v;
    __syncthreads();
    for (int o = 1; o < 1024; o <<= 1) {
        int t = (threadIdx.x >= o) ? sh[threadIdx.x - o] : 0;
        __syncthreads();
        sh[threadIdx.x] += t;
        __syncthreads();
    }
    if (i < N) rowptr[i] = sh[threadIdx.x] - v;
    if (threadIdx.x == 1023) bsum[blockIdx.x] = sh[1023];
}
__global__ void scan_bsum(int* bsum, int nb) {
    if (threadIdx.x == 0 && blockIdx.x == 0) {
        int acc = 0;
        for (int b = 0; b < nb; b++) { int t = bsum[b]; bsum[b] = acc; acc += t; }
    }
}
__global__ void add_off(int* __restrict__ rowptr, int* __restrict__ wp,
                        const int* __restrict__ bsum, int N, int E) {
    int i = blockIdx.x * blockDim.x + threadIdx.x;
    if (i < N) {
        int v = rowptr[i] + bsum[i >> 10];
        rowptr[i] = v;
        wp[i] = v;
    }
    if (i == 0) rowptr[N] = E;
}
__global__ void scatter_k(const int* __restrict__ src, const int* __restrict__ dst,
                          int* __restrict__ wp, int* __restrict__ csrc, int E) {
    int i = blockIdx.x * blockDim.x + threadIdx.x;
    if (i < E) {
        int pos = atomicAdd(&wp[dst[i]], 1);
        csrc[pos] = src[i];
    }
}

// ================= split / W-prep =================
__global__ void split_k(const float* __restrict__ v, __nv_bfloat16* __restrict__ hi,
                        __nv_bfloat16* __restrict__ lo, int n) {
    int i = blockIdx.x * blockDim.x + threadIdx.x;
    if (i < n) {
        float f = v[i];
        __nv_bfloat16 h = __float2bfloat16(f);
        hi[i] = h;
        lo[i] = __float2bfloat16(f - __bfloat162float(h));
    }
}
// W[k*J+j] -> Wt[j*K+k], zero-padded to J64 rows
__global__ void prepw_k(const float* __restrict__ W, __nv_bfloat16* __restrict__ hi,
                        __nv_bfloat16* __restrict__ lo, int K, int J, int J64) {
    int i = blockIdx.x * blockDim.x + threadIdx.x;
    if (i < K * J64) {
        int j = i / K, k = i % K;
        float f = (j < J) ? W[k * J + j] : 0.f;
        __nv_bfloat16 h = __float2bfloat16(f);
        hi[i] = h;
        lo[i] = __float2bfloat16(f - __bfloat162float(h));
    }
}

// ================= mma.sync bf16 GEMM with register-prefetch pipeline =================
#define MMA_BF16(d, a, b)                                                          \
    asm volatile(                                                                  \
        "mma.sync.aligned.m16n8k16.row.col.f32.bf16.bf16.f32 "                     \
        "{%0,%1,%2,%3},{%4,%5,%6,%7},{%8,%9},{%0,%1,%2,%3};"                       \
        : "+f"((d)[0]), "+f"((d)[1]), "+f"((d)[2]), "+f"((d)[3])                   \
        : "r"((a)[0]), "r"((a)[1]), "r"((a)[2]), "r"((a)[3]), "r"((b)[0]), "r"((b)[1]))

template <int K, int J>
__global__ __launch_bounds__(256) void gemm_mma(
    const __nv_bfloat16* __restrict__ Ahi, const __nv_bfloat16* __restrict__ Alo,
    const __nv_bfloat16* __restrict__ Bhi, const __nv_bfloat16* __restrict__ Blo,
    float* __restrict__ C, int M) {
    constexpr int BK = 32, STR = BK + 8;
    __shared__ __nv_bfloat16 sAh[128 * STR], sAl[128 * STR];
    __shared__ __nv_bfloat16 sBh[64 * STR], sBl[64 * STR];
    const int tid = threadIdx.x;
    const int wid = tid >> 5, lane = tid & 31;
    const int g = lane >> 2, t = lane & 3;
    const int wm = wid & 3, wn = wid >> 2;
    const int row0 = blockIdx.y * 128, col0 = blockIdx.x * 64;

    float acc[2][4][4];
#pragma unroll
    for (int am = 0; am < 2; am++)
#pragma unroll
        for (int an = 0; an < 4; an++)
#pragma unroll
            for (int q = 0; q < 4; q++) acc[am][an][q] = 0.f;

    // register staging: A 2 uint4 per thread per buf, B 1 per buf
    uint4 rah[2], ral[2], rbh, rbl;
    const int ar0 = tid >> 2, acb0 = (tid & 3) * 8;
    const int ar1 = (tid + 256) >> 2, acb1 = ((tid + 256) & 3) * 8;
    const int gra0 = min(row0 + ar0, M - 1), gra1 = min(row0 + ar1, M - 1);
    const int brr = tid >> 2, bcb = (tid & 3) * 8;

#define LOADREG(kb)                                                                  \
    do {                                                                             \
        rah[0] = *(const uint4*)&Ahi[(size_t)gra0 * K + (kb) + acb0];                \
        ral[0] = *(const uint4*)&Alo[(size_t)gra0 * K + (kb) + acb0];                \
        rah[1] = *(const uint4*)&Ahi[(size_t)gra1 * K + (kb) + acb1];                \
        ral[1] = *(const uint4*)&Alo[(size_t)gra1 * K + (kb) + acb1];                \
        rbh = *(const uint4*)&Bhi[(size_t)(col0 + brr) * K + (kb) + bcb];            \
        rbl = *(const uint4*)&Blo[(size_t)(col0 + brr) * K + (kb) + bcb];            \
    } while (0)

    LOADREG(0);
    for (int kb = 0; kb < K; kb += BK) {
        *(uint4*)&sAh[ar0 * STR + acb0] = rah[0];
        *(uint4*)&sAl[ar0 * STR + acb0] = ral[0];
        *(uint4*)&sAh[ar1 * STR + acb1] = rah[1];
        *(uint4*)&sAl[ar1 * STR + acb1] = ral[1];
        *(uint4*)&sBh[brr * STR + bcb] = rbh;
        *(uint4*)&sBl[brr * STR + bcb] = rbl;
        __syncthreads();
        if (kb + BK < K) LOADREG(kb + BK);
#pragma unroll
        for (int ks = 0; ks < BK / 16; ks++) {
            const int k0 = ks * 16;
            uint32_t ah[2][4], al_[2][4], bh[4][2], bl[4][2];
#pragma unroll
            for (int am = 0; am < 2; am++) {
                int rb = wm * 32 + am * 16;
                ah[am][0] = *(const uint32_t*)&sAh[(rb + g) * STR + k0 + 2 * t];
                ah[am][1] = *(const uint32_t*)&sAh[(rb + g + 8) * STR + k0 + 2 * t];
                ah[am][2] = *(const uint32_t*)&sAh[(rb + g) * STR + k0 + 2 * t + 8];
                ah[am][3] = *(const uint32_t*)&sAh[(rb + g + 8) * STR + k0 + 2 * t + 8];
                al_[am][0] = *(const uint32_t*)&sAl[(rb + g) * STR + k0 + 2 * t];
                al_[am][1] = *(const uint32_t*)&sAl[(rb + g + 8) * STR + k0 + 2 * t];
                al_[am][2] = *(const uint32_t*)&sAl[(rb + g) * STR + k0 + 2 * t + 8];
                al_[am][3] = *(const uint32_t*)&sAl[(rb + g + 8) * STR + k0 + 2 * t + 8];
            }
#pragma unroll
            for (int an = 0; an < 4; an++) {
                int c = wn * 32 + an * 8 + g;
                bh[an][0] = *(const uint32_t*)&sBh[c * STR + k0 + 2 * t];
                bh[an][1] = *(const uint32_t*)&sBh[c * STR + k0 + 2 * t + 8];
                bl[an][0] = *(const uint32_t*)&sBl[c * STR + k0 + 2 * t];
                bl[an][1] = *(const uint32_t*)&sBl[c * STR + k0 + 2 * t + 8];
            }
#pragma unroll
            for (int am = 0; am < 2; am++)
#pragma unroll
                for (int an = 0; an < 4; an++) {
                    MMA_BF16(acc[am][an], ah[am], bh[an]);
                    MMA_BF16(acc[am][an], ah[am], bl[an]);
                    MMA_BF16(acc[am][an], al_[am], bh[an]);
                }
        }
        __syncthreads();
    }
#pragma unroll
    for (int am = 0; am < 2; am++) {
        int r0 = row0 + wm * 32 + am * 16 + g;
#pragma unroll
        for (int an = 0; an < 4; an++) {
            int c = col0 + wn * 32 + an * 8 + 2 * t;
            if (c < J) {
                if (r0 < M)
                    *(float2*)&C[(size_t)r0 * J + c] = make_float2(acc[am][an][0], acc[am][an][1]);
                if (r0 + 8 < M)
                    *(float2*)&C[(size_t)(r0 + 8) * J + c] = make_float2(acc[am][an][2], acc[am][an][3]);
            }
        }
    }
#undef LOADREG
}

// ================= per-node attention scores (float4) =================
__device__ __forceinline__ float dot4(float4 a, float4 b) {
    return a.x * b.x + a.y * b.y + a.z * b.z + a.w * b.w;
}
template <int H, int D>
__global__ void scores_k(const float* __restrict__ feat,
                         const float* __restrict__ al,
                         const float* __restrict__ ar,
                         float* __restrict__ el, float* __restrict__ er, int N) {
    constexpr int HD = H * D;
    int warp = (blockIdx.x * blockDim.x + threadIdx.x) >> 5;
    int lane = threadIdx.x & 31;
    if (warp >= N) return;
    const float4* f4 = (const float4*)(feat + (size_t)warp * HD);
    const float4* al4 = (const float4*)al;
    const float4* ar4 = (const float4*)ar;

    if (HD == 256) {
        float4 fa = __ldg(f4 + lane), fb = __ldg(f4 + 32 + lane);
        float4 aa = __ldg(al4 + lane), ab = __ldg(al4 + 32 + lane);
        float4 ra = __ldg(ar4 + lane), rb = __ldg(ar4 + 32 + lane);
        float pla = dot4(fa, aa), plb = dot4(fb, ab);
        float pra = dot4(fa, ra), prb = dot4(fb, rb);
#pragma unroll
        for (int o = 8; o; o >>= 1) {
            pla += __shfl_xor_sync(0xffffffffu, pla, o);
            plb += __shfl_xor_sync(0xffffffffu, plb, o);
            pra += __shfl_xor_sync(0xffffffffu, pra, o);
            prb += __shfl_xor_sync(0xffffffffu, prb, o);
        }
        if (lane == 0)  { el[warp * 4 + 0] = pla; el[warp * 4 + 2] = plb;
                          er[warp * 4 + 0] = pra; er[warp * 4 + 2] = prb; }
        if (lane == 16) { el[warp * 4 + 1] = pla; el[warp * 4 + 3] = plb;
                          er[warp * 4 + 1] = pra; er[warp * 4 + 3] = prb; }
    } else {
        constexpr int NV = HD / 4;
        float pl = 0.f, pr = 0.f;
        if (lane < NV) {
            float4 f = __ldg(f4 + lane);
            pl = dot4(f, __ldg(al4 + lane));
            pr = dot4(f, __ldg(ar4 + lane));
        }
#pragma unroll
        for (int o = 16; o; o >>= 1) {
            pl += __shfl_xor_sync(0xffffffffu, pl, o);
            pr += __shfl_xor_sync(0xffffffffu, pr, o);
        }
        if (lane == 0) { el[warp] = pl; er[warp] = pr; }
    }
}

// ================= fused softmax + aggregate (CSR, one warp per dst node) ===========
template <int H, int D, int ACT, int WM>
__global__ __launch_bounds__(256) void agg_k(const int* __restrict__ rowptr,
                                             const int* __restrict__ csrc,
                                             const float* __restrict__ el,
                                             const float* __restrict__ er,
                                             const float* __restrict__ feat,
                                             float* __restrict__ out,
                                             __nv_bfloat16* __restrict__ ohi,
                                             __nv_bfloat16* __restrict__ olo, int N) {
    constexpr int HD = H * D;
    int warp = (blockIdx.x * blockDim.x + threadIdx.x) >> 5;
    int lane = threadIdx.x & 31;
    if (warp >= N) return;
    int beg = rowptr[warp];
    int end = rowptr[warp + 1];

    float erh[H];
    if (H == 4) {
        float4 t = __ldg((const float4*)er + warp);
        erh[0] = t.x; erh[1] = t.y; erh[2] = t.z; erh[3] = t.w;
    } else {
        erh[0] = __ldg(er + warp);
    }

    // ---- online softmax (max + den in one lane-strided pass) ----
    float m[H], den[H];
#pragma unroll
    for (int h = 0; h < H; h++) { m[h] = -1e30f; den[h] = 0.f; }
    for (int j = beg + lane; j < end; j += 32) {
        int s = __ldg(csrc + j);
        float eh[H];
        if (H == 4) {
            float4 t = __ldg((const float4*)el + s);
            eh[0] = t.x; eh[1] = t.y; eh[2] = t.z; eh[3] = t.w;
        } else eh[0] = __ldg(el + s);
#pragma unroll
        for (int h = 0; h < H; h++) {
            float v = eh[h] + erh[h];
            v = (v > 0.f) ? v : 0.2f * v;
            float nm = fmaxf(m[h], v);
            den[h] = den[h] * __expf(m[h] - nm) + __expf(v - nm);
            m[h] = nm;
        }
    }
    float inv[H];
#pragma unroll
    for (int h = 0; h < H; h++) {
#pragma unroll
        for (int o = 16; o; o >>= 1) {
            float mo = __shfl_xor_sync(0xffffffffu, m[h], o);
            float dn = __shfl_xor_sync(0xffffffffu, den[h], o);
            float nm = fmaxf(m[h], mo);
            den[h] = den[h] * __expf(m[h] - nm) + dn * __expf(mo - nm);
            m[h] = nm;
        }
        inv[h] = 1.f / fmaxf(den[h], 1e-9f);
    }

    if (HD == 256) {
        // whole warp per edge: lane covers cols lane*4 (head lane>>4) and 128+lane*4 (head 2+(lane>>4))
        const bool up = (lane & 16);
        const float m_a = up ? m[1] : m[0],  m_b = up ? m[3] : m[2];
        const float i_a = up ? inv[1] : inv[0], i_b = up ? inv[3] : inv[2];
        const float e_a = up ? erh[1] : erh[0], e_b = up ? erh[3] : erh[2];
        float4 acc0 = make_float4(0.f, 0.f, 0.f, 0.f);
        float4 acc1 = make_float4(0.f, 0.f, 0.f, 0.f);
        int j = beg;
        for (; j + 2 <= end; j += 2) {
            int s0 = __ldg(csrc + j), s1 = __ldg(csrc + j + 1);
            const float4* fr0 = (const float4*)(feat + (size_t)s0 * 256);
            const float4* fr1 = (const float4*)(feat + (size_t)s1 * 256);
            float4 f00 = __ldg(fr0 + lane), f01 = __ldg(fr0 + 32 + lane);
            float4 f10 = __ldg(fr1 + lane), f11 = __ldg(fr1 + 32 + lane);
            float4 e40 = __ldg((const float4*)el + s0);
            float4 e41 = __ldg((const float4*)el + s1);
            float v0a = (up ? e40.y : e40.x) + e_a; v0a = (v0a > 0.f) ? v0a : 0.2f * v0a;
            float v0b = (up ? e40.w : e40.z) + e_b; v0b = (v0b > 0.f) ? v0b : 0.2f * v0b;
            float v1a = (up ? e41.y : e41.x) + e_a; v1a = (v1a > 0.f) ? v1a : 0.2f * v1a;
            float v1b = (up ? e41.w : e41.z) + e_b; v1b = (v1b > 0.f) ? v1b : 0.2f * v1b;
            float a0a = __expf(v0a - m_a) * i_a, a0b = __expf(v0b - m_b) * i_b;
            float a1a = __expf(v1a - m_a) * i_a, a1b = __expf(v1b - m_b) * i_b;
            acc0.x += f00.x * a0a; acc0.y += f00.y * a0a; acc0.z += f00.z * a0a; acc0.w += f00.w * a0a;
            acc1.x += f01.x * a0b; acc1.y += f01.y * a0b; acc1.z += f01.z * a0b; acc1.w += f01.w * a0b;
            acc0.x += f10.x * a1a; acc0.y += f10.y * a1a; acc0.z += f10.z * a1a; acc0.w += f10.w * a1a;
            acc1.x += f11.x * a1b; acc1.y += f11.y * a1b; acc1.z += f11.z * a1b; acc1.w += f11.w * a1b;
        }
        if (j < end) {
            int s0 = __ldg(csrc + j);
            const float4* fr0 = (const float4*)(feat + (size_t)s0 * 256);
            float4 f00 = __ldg(fr0 + lane), f01 = __ldg(fr0 + 32 + lane);
            float4 e40 = __ldg((const float4*)el + s0);
            float v0a = (up ? e40.y : e40.x) + e_a; v0a = (v0a > 0.f) ? v0a : 0.2f * v0a;
            float v0b = (up ? e40.w : e40.z) + e_b; v0b = (v0b > 0.f) ? v0b : 0.2f * v0b;
            float a0a = __expf(v0a - m_a) * i_a, a0b = __expf(v0b - m_b) * i_b;
            acc0.x += f00.x * a0a; acc0.y += f00.y * a0a; acc0.z += f00.z * a0a; acc0.w += f00.w * a0a;
            acc1.x += f01.x * a0b; acc1.y += f01.y * a0b; acc1.z += f01.z * a0b; acc1.w += f01.w * a0b;
        }
        // write 2 float4 chunks
#pragma unroll
        for (int q = 0; q < 2; q++) {
            float4 v = q ? acc1 : acc0;
            if (ACT) {
                v.x = (v.x > 0.f) ? v.x : expm1f(v.x);
                v.y = (v.y > 0.f) ? v.y : expm1f(v.y);
                v.z = (v.z > 0.f) ? v.z : expm1f(v.z);
                v.w = (v.w > 0.f) ? v.w : expm1f(v.w);
            }
            size_t idx = (size_t)warp * 256 + q * 128 + lane * 4;
            if (WM == 0) {
                *(float4*)(out + idx) = v;
            } else {
                __nv_bfloat16 hx = __float2bfloat16(v.x), hy = __float2bfloat16(v.y);
                __nv_bfloat16 hz = __float2bfloat16(v.z), hw = __float2bfloat16(v.w);
                __nv_bfloat162* ph = (__nv_bfloat162*)(ohi + idx);
                __nv_bfloat162* pl = (__nv_bfloat162*)(olo + idx);
                ph[0] = __nv_bfloat162(hx, hy);
                ph[1] = __nv_bfloat162(hz, hw);
                pl[0] = __nv_bfloat162(__float2bfloat16(v.x - __bfloat162float(hx)),
                                       __float2bfloat16(v.y - __bfloat162float(hy)));
                pl[1] = __nv_bfloat162(__float2bfloat16(v.z - __bfloat162float(hz)),
                                       __float2bfloat16(v.w - __bfloat162float(hw)));
            }
        }
    } else {
        // H==1, two 16-lane gangs, 2 edges in flight
        constexpr int NV = HD / 4;
        const int gp = lane >> 4, gl = lane & 15;
        const float m0 = m[0], i0 = inv[0], e0 = erh[0];
        float4 acc = make_float4(0.f, 0.f, 0.f, 0.f);
        for (int j = beg + gp; j < end; j += 2) {
            int s = __ldg(csrc + j);
            float elv = __ldg(el + s);
            float4 f = make_float4(0.f, 0.f, 0.f, 0.f);
            if (gl < NV) f = __ldg((const float4*)(feat + (size_t)s * HD) + gl);
            float v = elv + e0;
            v = (v > 0.f) ? v : 0.2f * v;
            float a = __expf(v - m0) * i0;
            acc.x += f.x * a; acc.y += f.y * a; acc.z += f.z * a; acc.w += f.w * a;
        }
        acc.x += __shfl_xor_sync(0xffffffffu, acc.x, 16);
        acc.y += __shfl_xor_sync(0xffffffffu, acc.y, 16);
        acc.z += __shfl_xor_sync(0xffffffffu, acc.z, 16);
        acc.w += __shfl_xor_sync(0xffffffffu, acc.w, 16);
        if (lane < NV) {
            if (ACT) {
                acc.x = (acc.x > 0.f) ? acc.x : expm1f(acc.x);
                acc.y = (acc.y > 0.f) ? acc.y : expm1f(acc.y);
                acc.z = (acc.z > 0.f) ? acc.z : expm1f(acc.z);
                acc.w = (acc.w > 0.f) ? acc.w : expm1f(acc.w);
            }
            size_t idx = (size_t)warp * HD + lane * 4;
            if (WM == 0) {
                *(float4*)(out + idx) = acc;
            } else {
                __nv_bfloat16 hx = __float2bfloat16(acc.x), hy = __float2bfloat16(acc.y);
                __nv_bfloat16 hz = __float2bfloat16(acc.z), hw = __float2bfloat16(acc.w);
                __nv_bfloat162* ph = (__nv_bfloat162*)(ohi + idx);
                __nv_bfloat162* pl = (__nv_bfloat162*)(olo + idx);
                ph[0] = __nv_bfloat162(hx, hy);
                ph[1] = __nv_bfloat162(hz, hw);
                pl[0] = __nv_bfloat162(__float2bfloat16(acc.x - __bfloat162float(hx)),
                                       __float2bfloat16(acc.y - __bfloat162float(hy)));
                pl[1] = __nv_bfloat162(__float2bfloat16(acc.z - __bfloat162float(hz)),
                                       __float2bfloat16(acc.w - __bfloat162float(hw)));
            }
        }
    }
}

// ================= one full GATConv layer =================
template <int K, int H, int D, int ACT, int WM>
static void run_layer(const __nv_bfloat16* Ahi, const __nv_bfloat16* Alo,
                      const float* W, const float* al, const float* ar,
                      float* feat, float* outf, __nv_bfloat16* ohi, __nv_bfloat16* olo,
                      int N, const int* rowptr, const int* csrc, float* el, float* er,
                      __nv_bfloat16* whi, __nv_bfloat16* wlo) {
    constexpr int J = H * D;
    constexpr int J64 = (J + 63) / 64 * 64;
    prepw_k<<<(K * J64 + 255) / 256, 256>>>(W, whi, wlo, K, J, J64);
    dim3 grid(J64 / 64, (N + 127) / 128);
    gemm_mma<K, J><<<grid, 256>>>(Ahi, Alo, whi, wlo, feat, N);
    scores_k<H, D><<<(N * 32 + 255) / 256, 256>>>(feat, al, ar, el, er, N);
    agg_k<H, D, ACT, WM><<<(N * 32 + 255) / 256, 256>>>(rowptr, csrc, el, er, feat,
                                                        outf, ohi, olo, N);
}

extern "C" void kernel_launch(void* const* d_in, const int* in_sizes, int n_in,
                              void* d_out, int out_size) {
    const float* x    = (const float*)d_in[0];
    const int*   src  = (const int*)d_in[1];
    const int*   dst  = (const int*)d_in[2];
    const float* W00  = (const float*)d_in[3];
    const float* a00l = (const float*)d_in[4];
    const float* a00r = (const float*)d_in[5];
    const float* W01  = (const float*)d_in[6];
    const float* a01l = (const float*)d_in[7];
    const float* a01r = (const float*)d_in[8];
    const float* W0f  = (const float*)d_in[9];
    const float* a0fl = (const float*)d_in[10];
    const float* a0fr = (const float*)d_in[11];
    const float* W10  = (const float*)d_in[12];
    const float* a10l = (const float*)d_in[13];
    const float* a10r = (const float*)d_in[14];
    const float* W1f  = (const float*)d_in[15];
    const float* a1fl = (const float*)d_in[16];
    const float* a1fr = (const float*)d_in[17];
    const float* W1o  = (const float*)d_in[18];
    const float* a1ol = (const float*)d_in[19];
    const float* a1or = (const float*)d_in[20];
    float* out = (float*)d_out;

    const int N = in_sizes[0] / 256;
    const int E = in_sizes[1];

    float *feat, *el, *er;
    __nv_bfloat16 *xhi, *xlo, *hhi, *hlo, *whi, *wlo;
    int *deg, *rowptr, *wp, *bsum, *csrc;
    cudaGetSymbolAddress((void**)&feat, g_feat);
    cudaGetSymbolAddress((void**)&el, g_el);
    cudaGetSymbolAddress((void**)&er, g_er);
    cudaGetSymbolAddress((void**)&xhi, g_xhi);
    cudaGetSymbolAddress((void**)&xlo, g_xlo);
    cudaGetSymbolAddress((void**)&hhi, g_hhi);
    cudaGetSymbolAddress((void**)&hlo, g_hlo);
    cudaGetSymbolAddress((void**)&whi, g_whi);
    cudaGetSymbolAddress((void**)&wlo, g_wlo);
    cudaGetSymbolAddress((void**)&deg, g_deg);
    cudaGetSymbolAddress((void**)&rowptr, g_rowptr);
    cudaGetSymbolAddress((void**)&wp, g_wp);
    cudaGetSymbolAddress((void**)&bsum, g_bsum);
    cudaGetSymbolAddress((void**)&csrc, g_csrc);

    // ---- x split + dst-CSR build (shared by all layers) ----
    split_k<<<((long)N * 256 + 255) / 256, 256>>>(x, xhi, xlo, N * 256);
    zero_deg<<<(N + 255) / 256, 256>>>(deg, N);
    hist_k<<<(E + 255) / 256, 256>>>(dst, deg, E);
    int ntiles = (N + 1023) / 1024;
    scan_tiles<<<ntiles, 1024>>>(deg, rowptr, bsum, N);
    scan_bsum<<<1, 32>>>(bsum, ntiles);
    add_off<<<(N + 255) / 256, 256>>>(rowptr, wp, bsum, N, E);
    scatter_k<<<(E + 255) / 256, 256>>>(src, dst, wp, csrc, E);

    // ---- branch 0 ----
    run_layer<256, 4, 64, 1, 1>(xhi, xlo, W00, a00l, a00r, feat, nullptr, hhi, hlo,
                                N, rowptr, csrc, el, er, whi, wlo);
    run_layer<256, 1, 64, 1, 1>(hhi, hlo, W01, a01l, a01r, feat, nullptr, hhi, hlo,
                                N, rowptr, csrc, el, er, whi, wlo);
    run_layer<64, 1, 40, 0, 0>(hhi, hlo, W0f, a0fl, a0fr, feat, out, nullptr, nullptr,
                               N, rowptr, csrc, el, er, whi, wlo);

    // ---- branch 1 ----
    run_layer<256, 4, 64, 1, 1>(xhi, xlo, W10, a10l, a10r, feat, nullptr, hhi, hlo,
                                N, rowptr, csrc, el, er, whi, wlo);
    run_layer<256, 1, 64, 0, 1>(hhi, hlo, W1f, a1fl, a1fr, feat, nullptr, hhi, hlo,
                                N, rowptr, csrc, el, er, whi, wlo);
    run_layer<64, 1, 40, 1, 0>(hhi, hlo, W1o, a1ol, a1or, feat, out + (size_t)N * CC,
                               nullptr, nullptr, N, rowptr, csrc, el, er, whi, wlo);
}

// round 12
// speedup vs baseline: 4.0688x; 1.0662x over previous
#include <cuda_runtime.h>
#include <cuda_bf16.h>
#include <math.h>
#include <stdint.h>

#define NN 50000
#define EE 800000
#define CC 40

// ---------------- scratch (device globals; no allocations allowed) ----------------
__device__ __align__(16) float g_feat[NN * 256];           // GEMM output (fp32)
__device__ __align__(16) float g_el[NN * 4];
__device__ __align__(16) float g_er[NN * 4];
__device__ __align__(16) __nv_bfloat16 g_xhi[NN * 256];    // x split (built once)
__device__ __align__(16) __nv_bfloat16 g_xlo[NN * 256];
__device__ __align__(16) __nv_bfloat16 g_hhi[NN * 256];    // intermediate split
__device__ __align__(16) __nv_bfloat16 g_hlo[NN * 256];
__device__ __align__(16) __nv_bfloat16 g_whi[256 * 256];   // W^T split (padded)
__device__ __align__(16) __nv_bfloat16 g_wlo[256 * 256];
__device__ int   g_deg[NN];
__device__ int   g_rowptr[NN + 1];
__device__ int   g_wp[NN];
__device__ int   g_bsum[64];
__device__ int   g_csrc[EE];

__device__ __forceinline__ uint32_t s2u(const void* p) {
    uint32_t a;
    asm("{ .reg .u64 t; cvta.to.shared.u64 t, %1; cvt.u32.u64 %0, t; }" : "=r"(a) : "l"(p));
    return a;
}

// ================= CSR build =================
__global__ void zero_deg(int* deg, int N) {
    int i = blockIdx.x * blockDim.x + threadIdx.x;
    if (i < N) deg[i] = 0;
}
__global__ void hist_k(const int* __restrict__ dst, int* __restrict__ deg, int E) {
    int i = blockIdx.x * blockDim.x + threadIdx.x;
    if (i < E) atomicAdd(&deg[dst[i]], 1);
}
__global__ void scan_tiles(const int* __restrict__ deg, int* __restrict__ rowptr,
                           int* __restrict__ bsum, int N) {
    __shared__ int sh[1024];
    int i = blockIdx.x * 1024 + threadIdx.x;
    int v = (i < N) ? deg[i] : 0;
    sh[threadIdx.x] = v;
    __syncthreads();
    for (int o = 1; o < 1024; o <<= 1) {
        int t = (threadIdx.x >= o) ? sh[threadIdx.x - o] : 0;
        __syncthreads();
        sh[threadIdx.x] += t;
        __syncthreads();
    }
    if (i < N) rowptr[i] = sh[threadIdx.x] - v;
    if (threadIdx.x == 1023) bsum[blockIdx.x] = sh[1023];
}
__global__ void scan_bsum(int* bsum, int nb) {
    if (threadIdx.x == 0 && blockIdx.x == 0) {
        int acc = 0;
        for (int b = 0; b < nb; b++) { int t = bsum[b]; bsum[b] = acc; acc += t; }
    }
}
__global__ void add_off(int* __restrict__ rowptr, int* __restrict__ wp,
                        const int* __restrict__ bsum, int N, int E) {
    int i = blockIdx.x * blockDim.x + threadIdx.x;
    if (i < N) {
        int v = rowptr[i] + bsum[i >> 10];
        rowptr[i] = v;
        wp[i] = v;
    }
    if (i == 0) rowptr[N] = E;
}
__global__ void scatter_k(const int* __restrict__ src, const int* __restrict__ dst,
                          int* __restrict__ wp, int* __restrict__ csrc, int E) {
    int i = blockIdx.x * blockDim.x + threadIdx.x;
    if (i < E) {
        int pos = atomicAdd(&wp[dst[i]], 1);
        csrc[pos] = src[i];
    }
}

// ================= split / W-prep =================
__global__ void split_k(const float* __restrict__ v, __nv_bfloat16* __restrict__ hi,
                        __nv_bfloat16* __restrict__ lo, int n) {
    int i = blockIdx.x * blockDim.x + threadIdx.x;
    if (i < n) {
        float f = v[i];
        __nv_bfloat16 h = __float2bfloat16(f);
        hi[i] = h;
        lo[i] = __float2bfloat16(f - __bfloat162float(h));
    }
}
__global__ void prepw_k(const float* __restrict__ W, __nv_bfloat16* __restrict__ hi,
                        __nv_bfloat16* __restrict__ lo, int K, int J, int J64) {
    int i = blockIdx.x * blockDim.x + threadIdx.x;
    if (i < K * J64) {
        int j = i / K, k = i % K;
        float f = (j < J) ? W[k * J + j] : 0.f;
        __nv_bfloat16 h = __float2bfloat16(f);
        hi[i] = h;
        lo[i] = __float2bfloat16(f - __bfloat162float(h));
    }
}

// ================= mma.sync bf16 GEMM, ldmatrix, fused scores epilogue =================
#define MMA_BF16(d, a, b)                                                          \
    asm volatile(                                                                  \
        "mma.sync.aligned.m16n8k16.row.col.f32.bf16.bf16.f32 "                     \
        "{%0,%1,%2,%3},{%4,%5,%6,%7},{%8,%9},{%0,%1,%2,%3};"                       \
        : "+f"((d)[0]), "+f"((d)[1]), "+f"((d)[2]), "+f"((d)[3])                   \
        : "r"((a)[0]), "r"((a)[1]), "r"((a)[2]), "r"((a)[3]), "r"((b)[0]), "r"((b)[1]))
#define LDSM4(r, addr)                                                             \
    asm volatile("ldmatrix.sync.aligned.m8n8.x4.shared.b16 {%0,%1,%2,%3}, [%4];"   \
        : "=r"((r)[0]), "=r"((r)[1]), "=r"((r)[2]), "=r"((r)[3]) : "r"(addr))

template <int K, int J, int D>
__global__ __launch_bounds__(256) void gemm_mma(
    const __nv_bfloat16* __restrict__ Ahi, const __nv_bfloat16* __restrict__ Alo,
    const __nv_bfloat16* __restrict__ Bhi, const __nv_bfloat16* __restrict__ Blo,
    const float* __restrict__ alv, const float* __restrict__ arv,
    float* __restrict__ C, float* __restrict__ el, float* __restrict__ er, int M) {
    constexpr int H = J / D;
    constexpr int BK = 32, STR = BK + 8;
    __shared__ __nv_bfloat16 sAh[128 * STR], sAl[128 * STR];
    __shared__ __nv_bfloat16 sBh[64 * STR], sBl[64 * STR];
    const int tid = threadIdx.x;
    const int wid = tid >> 5, lane = tid & 31;
    const int g = lane >> 2, t = lane & 3;
    const int wm = wid & 3, wn = wid >> 2;
    const int row0 = blockIdx.y * 128, col0 = blockIdx.x * 64;

    float acc[2][4][4];
#pragma unroll
    for (int am = 0; am < 2; am++)
#pragma unroll
        for (int an = 0; an < 4; an++)
#pragma unroll
            for (int q = 0; q < 4; q++) acc[am][an][q] = 0.f;

    // register staging for global->smem
    uint4 rah[2], ral[2], rbh, rbl;
    const int ar0 = tid >> 2, acb0 = (tid & 3) * 8;
    const int ar1 = (tid + 256) >> 2, acb1 = ((tid + 256) & 3) * 8;
    const int gra0 = min(row0 + ar0, M - 1), gra1 = min(row0 + ar1, M - 1);
    const int brr = tid >> 2, bcb = (tid & 3) * 8;

#define LOADREG(kb)                                                                  \
    do {                                                                             \
        rah[0] = *(const uint4*)&Ahi[(size_t)gra0 * K + (kb) + acb0];                \
        ral[0] = *(const uint4*)&Alo[(size_t)gra0 * K + (kb) + acb0];                \
        rah[1] = *(const uint4*)&Ahi[(size_t)gra1 * K + (kb) + acb1];                \
        ral[1] = *(const uint4*)&Alo[(size_t)gra1 * K + (kb) + acb1];                \
        rbh = *(const uint4*)&Bhi[(size_t)(col0 + brr) * K + (kb) + bcb];            \
        rbl = *(const uint4*)&Blo[(size_t)(col0 + brr) * K + (kb) + bcb];            \
    } while (0)

    // ldmatrix lane addressing
    const uint32_t uAh = s2u(sAh), uAl = s2u(sAl), uBh = s2u(sBh), uBl = s2u(sBl);
    const int lar = ((lane >> 3) & 1) * 8 + (lane & 7);   // A row within 16
    const int lak = (lane >> 4) * 8;                       // A k offset
    const uint32_t aoff = (uint32_t)((lar * STR + lak) * 2);
    const uint32_t amo0 = (uint32_t)((wm * 32) * STR * 2);
    const uint32_t amo1 = amo0 + (uint32_t)(16 * STR * 2);
    const int bn = lane & 7, bk2 = ((lane >> 3) & 1) * 8, bsel = lane >> 4;
    uint32_t boff[2];
#pragma unroll
    for (int p = 0; p < 2; p++)
        boff[p] = (uint32_t)(((wn * 32 + (2 * p + bsel) * 8 + bn) * STR + bk2) * 2);

    LOADREG(0);
    for (int kb = 0; kb < K; kb += BK) {
        *(uint4*)&sAh[ar0 * STR + acb0] = rah[0];
        *(uint4*)&sAl[ar0 * STR + acb0] = ral[0];
        *(uint4*)&sAh[ar1 * STR + acb1] = rah[1];
        *(uint4*)&sAl[ar1 * STR + acb1] = ral[1];
        *(uint4*)&sBh[brr * STR + bcb] = rbh;
        *(uint4*)&sBl[brr * STR + bcb] = rbl;
        __syncthreads();
        if (kb + BK < K) LOADREG(kb + BK);
#pragma unroll
        for (int ks = 0; ks < BK / 16; ks++) {
            const uint32_t k2 = (uint32_t)(ks * 16 * 2);
            uint32_t ah[2][4], al_[2][4], bh[2][4], bl[2][4];
            LDSM4(ah[0], uAh + amo0 + aoff + k2);
            LDSM4(ah[1], uAh + amo1 + aoff + k2);
            LDSM4(al_[0], uAl + amo0 + aoff + k2);
            LDSM4(al_[1], uAl + amo1 + aoff + k2);
            LDSM4(bh[0], uBh + boff[0] + k2);
            LDSM4(bh[1], uBh + boff[1] + k2);
            LDSM4(bl[0], uBl + boff[0] + k2);
            LDSM4(bl[1], uBl + boff[1] + k2);
#pragma unroll
            for (int am = 0; am < 2; am++)
#pragma unroll
                for (int an = 0; an < 4; an++) {
                    uint32_t* bph = &bh[an >> 1][(an & 1) * 2];
                    uint32_t* bpl = &bl[an >> 1][(an & 1) * 2];
                    MMA_BF16(acc[am][an], ah[am], bph);
                    MMA_BF16(acc[am][an], ah[am], bpl);
                    MMA_BF16(acc[am][an], al_[am], bph);
                }
        }
        __syncthreads();
    }
#undef LOADREG

    // ---- store C + fused attention scores ----
    const int head = (col0 + wn * 32) / D;
    // per-thread column attention coefficients (c may exceed J on padded cols -> 0)
    float alc[4][2], arc[4][2];
#pragma unroll
    for (int an = 0; an < 4; an++) {
        int c = col0 + wn * 32 + an * 8 + 2 * t;
#pragma unroll
        for (int q = 0; q < 2; q++) {
            alc[an][q] = (c + q < J) ? __ldg(alv + c + q) : 0.f;
            arc[an][q] = (c + q < J) ? __ldg(arv + c + q) : 0.f;
        }
    }
#pragma unroll
    for (int am = 0; am < 2; am++) {
        int r0 = row0 + wm * 32 + am * 16 + g;
        float pl0 = 0.f, pr0 = 0.f, pl8 = 0.f, pr8 = 0.f;
#pragma unroll
        for (int an = 0; an < 4; an++) {
            int c = col0 + wn * 32 + an * 8 + 2 * t;
            if (c < J) {
                if (r0 < M)
                    *(float2*)&C[(size_t)r0 * J + c] = make_float2(acc[am][an][0], acc[am][an][1]);
                if (r0 + 8 < M)
                    *(float2*)&C[(size_t)(r0 + 8) * J + c] = make_float2(acc[am][an][2], acc[am][an][3]);
            }
            pl0 += acc[am][an][0] * alc[an][0] + acc[am][an][1] * alc[an][1];
            pr0 += acc[am][an][0] * arc[an][0] + acc[am][an][1] * arc[an][1];
            pl8 += acc[am][an][2] * alc[an][0] + acc[am][an][3] * alc[an][1];
            pr8 += acc[am][an][2] * arc[an][0] + acc[am][an][3] * arc[an][1];
        }
        // quad reduce over t
#pragma unroll
        for (int o = 1; o < 4; o <<= 1) {
            pl0 += __shfl_xor_sync(0xffffffffu, pl0, o);
            pr0 += __shfl_xor_sync(0xffffffffu, pr0, o);
            pl8 += __shfl_xor_sync(0xffffffffu, pl8, o);
            pr8 += __shfl_xor_sync(0xffffffffu, pr8, o);
        }
        if (t == 0) {
            if (r0 < M) {
                atomicAdd(&el[r0 * H + head], pl0);
                atomicAdd(&er[r0 * H + head], pr0);
            }
            if (r0 + 8 < M) {
                atomicAdd(&el[(r0 + 8) * H + head], pl8);
                atomicAdd(&er[(r0 + 8) * H + head], pr8);
            }
        }
    }
}

// ================= fused softmax + aggregate (CSR, one warp per dst node) ===========
template <int H, int D, int ACT, int WM>
__global__ __launch_bounds__(256) void agg_k(const int* __restrict__ rowptr,
                                             const int* __restrict__ csrc,
                                             const float* __restrict__ el,
                                             const float* __restrict__ er,
                                             const float* __restrict__ feat,
                                             float* __restrict__ out,
                                             __nv_bfloat16* __restrict__ ohi,
                                             __nv_bfloat16* __restrict__ olo, int N) {
    constexpr int HD = H * D;
    int warp = (blockIdx.x * blockDim.x + threadIdx.x) >> 5;
    int lane = threadIdx.x & 31;
    if (warp >= N) return;
    int beg = rowptr[warp];
    int end = rowptr[warp + 1];

    float erh[H];
    if (H == 4) {
        float4 t = __ldg((const float4*)er + warp);
        erh[0] = t.x; erh[1] = t.y; erh[2] = t.z; erh[3] = t.w;
    } else {
        erh[0] = __ldg(er + warp);
    }

    // ---- online softmax (max + den in one lane-strided pass) ----
    float m[H], den[H];
#pragma unroll
    for (int h = 0; h < H; h++) { m[h] = -1e30f; den[h] = 0.f; }
    for (int j = beg + lane; j < end; j += 32) {
        int s = __ldg(csrc + j);
        float eh[H];
        if (H == 4) {
            float4 t = __ldg((const float4*)el + s);
            eh[0] = t.x; eh[1] = t.y; eh[2] = t.z; eh[3] = t.w;
        } else eh[0] = __ldg(el + s);
#pragma unroll
        for (int h = 0; h < H; h++) {
            float v = eh[h] + erh[h];
            v = (v > 0.f) ? v : 0.2f * v;
            float nm = fmaxf(m[h], v);
            den[h] = den[h] * __expf(m[h] - nm) + __expf(v - nm);
            m[h] = nm;
        }
    }
    float inv[H];
#pragma unroll
    for (int h = 0; h < H; h++) {
#pragma unroll
        for (int o = 16; o; o >>= 1) {
            float mo = __shfl_xor_sync(0xffffffffu, m[h], o);
            float dn = __shfl_xor_sync(0xffffffffu, den[h], o);
            float nm = fmaxf(m[h], mo);
            den[h] = den[h] * __expf(m[h] - nm) + dn * __expf(mo - nm);
            m[h] = nm;
        }
        inv[h] = 1.f / fmaxf(den[h], 1e-9f);
    }

    if (HD == 256) {
        const bool up = (lane & 16);
        const float m_a = up ? m[1] : m[0],  m_b = up ? m[3] : m[2];
        const float i_a = up ? inv[1] : inv[0], i_b = up ? inv[3] : inv[2];
        const float e_a = up ? erh[1] : erh[0], e_b = up ? erh[3] : erh[2];
        float4 acc0 = make_float4(0.f, 0.f, 0.f, 0.f);
        float4 acc1 = make_float4(0.f, 0.f, 0.f, 0.f);
        int j = beg;
        for (; j + 2 <= end; j += 2) {
            int s0 = __ldg(csrc + j), s1 = __ldg(csrc + j + 1);
            const float4* fr0 = (const float4*)(feat + (size_t)s0 * 256);
            const float4* fr1 = (const float4*)(feat + (size_t)s1 * 256);
            float4 f00 = __ldg(fr0 + lane), f01 = __ldg(fr0 + 32 + lane);
            float4 f10 = __ldg(fr1 + lane), f11 = __ldg(fr1 + 32 + lane);
            float4 e40 = __ldg((const float4*)el + s0);
            float4 e41 = __ldg((const float4*)el + s1);
            float v0a = (up ? e40.y : e40.x) + e_a; v0a = (v0a > 0.f) ? v0a : 0.2f * v0a;
            float v0b = (up ? e40.w : e40.z) + e_b; v0b = (v0b > 0.f) ? v0b : 0.2f * v0b;
            float v1a = (up ? e41.y : e41.x) + e_a; v1a = (v1a > 0.f) ? v1a : 0.2f * v1a;
            float v1b = (up ? e41.w : e41.z) + e_b; v1b = (v1b > 0.f) ? v1b : 0.2f * v1b;
            float a0a = __expf(v0a - m_a) * i_a, a0b = __expf(v0b - m_b) * i_b;
            float a1a = __expf(v1a - m_a) * i_a, a1b = __expf(v1b - m_b) * i_b;
            acc0.x += f00.x * a0a; acc0.y += f00.y * a0a; acc0.z += f00.z * a0a; acc0.w += f00.w * a0a;
            acc1.x += f01.x * a0b; acc1.y += f01.y * a0b; acc1.z += f01.z * a0b; acc1.w += f01.w * a0b;
            acc0.x += f10.x * a1a; acc0.y += f10.y * a1a; acc0.z += f10.z * a1a; acc0.w += f10.w * a1a;
            acc1.x += f11.x * a1b; acc1.y += f11.y * a1b; acc1.z += f11.z * a1b; acc1.w += f11.w * a1b;
        }
        if (j < end) {
            int s0 = __ldg(csrc + j);
            const float4* fr0 = (const float4*)(feat + (size_t)s0 * 256);
            float4 f00 = __ldg(fr0 + lane), f01 = __ldg(fr0 + 32 + lane);
            float4 e40 = __ldg((const float4*)el + s0);
            float v0a = (up ? e40.y : e40.x) + e_a; v0a = (v0a > 0.f) ? v0a : 0.2f * v0a;
            float v0b = (up ? e40.w : e40.z) + e_b; v0b = (v0b > 0.f) ? v0b : 0.2f * v0b;
            float a0a = __expf(v0a - m_a) * i_a, a0b = __expf(v0b - m_b) * i_b;
            acc0.x += f00.x * a0a; acc0.y += f00.y * a0a; acc0.z += f00.z * a0a; acc0.w += f00.w * a0a;
            acc1.x += f01.x * a0b; acc1.y += f01.y * a0b; acc1.z += f01.z * a0b; acc1.w += f01.w * a0b;
        }
#pragma unroll
        for (int q = 0; q < 2; q++) {
            float4 v = q ? acc1 : acc0;
            if (ACT) {
                v.x = (v.x > 0.f) ? v.x : expm1f(v.x);
                v.y = (v.y > 0.f) ? v.y : expm1f(v.y);
                v.z = (v.z > 0.f) ? v.z : expm1f(v.z);
                v.w = (v.w > 0.f) ? v.w : expm1f(v.w);
            }
            size_t idx = (size_t)warp * 256 + q * 128 + lane * 4;
            if (WM == 0) {
                *(float4*)(out + idx) = v;
            } else {
                __nv_bfloat16 hx = __float2bfloat16(v.x), hy = __float2bfloat16(v.y);
                __nv_bfloat16 hz = __float2bfloat16(v.z), hw = __float2bfloat16(v.w);
                __nv_bfloat162* ph = (__nv_bfloat162*)(ohi + idx);
                __nv_bfloat162* pl = (__nv_bfloat162*)(olo + idx);
                ph[0] = __nv_bfloat162(hx, hy);
                ph[1] = __nv_bfloat162(hz, hw);
                pl[0] = __nv_bfloat162(__float2bfloat16(v.x - __bfloat162float(hx)),
                                       __float2bfloat16(v.y - __bfloat162float(hy)));
                pl[1] = __nv_bfloat162(__float2bfloat16(v.z - __bfloat162float(hz)),
                                       __float2bfloat16(v.w - __bfloat162float(hw)));
            }
        }
    } else {
        // H==1: two 16-lane gangs, each unrolled 2 edges -> 4 edges in flight per warp
        constexpr int NV = HD / 4;
        const int gp = lane >> 4, gl = lane & 15;
        const float m0 = m[0], i0 = inv[0], e0 = erh[0];
        float4 acc = make_float4(0.f, 0.f, 0.f, 0.f);
        int j = beg + gp;
        for (; j + 2 < end; j += 4) {
            int s0 = __ldg(csrc + j), s1 = __ldg(csrc + j + 2);
            float el0 = __ldg(el + s0), el1 = __ldg(el + s1);
            float4 f0 = make_float4(0.f, 0.f, 0.f, 0.f);
            float4 f1 = make_float4(0.f, 0.f, 0.f, 0.f);
            if (gl < NV) {
                f0 = __ldg((const float4*)(feat + (size_t)s0 * HD) + gl);
                f1 = __ldg((const float4*)(feat + (size_t)s1 * HD) + gl);
            }
            float v0 = el0 + e0; v0 = (v0 > 0.f) ? v0 : 0.2f * v0;
            float v1 = el1 + e0; v1 = (v1 > 0.f) ? v1 : 0.2f * v1;
            float a0 = __expf(v0 - m0) * i0, a1 = __expf(v1 - m0) * i0;
            acc.x += f0.x * a0 + f1.x * a1;
            acc.y += f0.y * a0 + f1.y * a1;
            acc.z += f0.z * a0 + f1.z * a1;
            acc.w += f0.w * a0 + f1.w * a1;
        }
        if (j < end) {
            int s0 = __ldg(csrc + j);
            float el0 = __ldg(el + s0);
            float4 f0 = make_float4(0.f, 0.f, 0.f, 0.f);
            if (gl < NV) f0 = __ldg((const float4*)(feat + (size_t)s0 * HD) + gl);
            float v0 = el0 + e0; v0 = (v0 > 0.f) ? v0 : 0.2f * v0;
            float a0 = __expf(v0 - m0) * i0;
            acc.x += f0.x * a0; acc.y += f0.y * a0; acc.z += f0.z * a0; acc.w += f0.w * a0;
        }
        acc.x += __shfl_xor_sync(0xffffffffu, acc.x, 16);
        acc.y += __shfl_xor_sync(0xffffffffu, acc.y, 16);
        acc.z += __shfl_xor_sync(0xffffffffu, acc.z, 16);
        acc.w += __shfl_xor_sync(0xffffffffu, acc.w, 16);
        if (lane < NV) {
            if (ACT) {
                acc.x = (acc.x > 0.f) ? acc.x : expm1f(acc.x);
                acc.y = (acc.y > 0.f) ? acc.y : expm1f(acc.y);
                acc.z = (acc.z > 0.f) ? acc.z : expm1f(acc.z);
                acc.w = (acc.w > 0.f) ? acc.w : expm1f(acc.w);
            }
            size_t idx = (size_t)warp * HD + lane * 4;
            if (WM == 0) {
                *(float4*)(out + idx) = acc;
            } else {
                __nv_bfloat16 hx = __float2bfloat16(acc.x), hy = __float2bfloat16(acc.y);
                __nv_bfloat16 hz = __float2bfloat16(acc.z), hw = __float2bfloat16(acc.w);
                __nv_bfloat162* ph = (__nv_bfloat162*)(ohi + idx);
                __nv_bfloat162* pl = (__nv_bfloat162*)(olo + idx);
                ph[0] = __nv_bfloat162(hx, hy);
                ph[1] = __nv_bfloat162(hz, hw);
                pl[0] = __nv_bfloat162(__float2bfloat16(acc.x - __bfloat162float(hx)),
                                       __float2bfloat16(acc.y - __bfloat162float(hy)));
                pl[1] = __nv_bfloat162(__float2bfloat16(acc.z - __bfloat162float(hz)),
                                       __float2bfloat16(acc.w - __bfloat162float(hw)));
            }
        }
    }
}

// ================= one full GATConv layer =================
template <int K, int H, int D, int ACT, int WM>
static void run_layer(const __nv_bfloat16* Ahi, const __nv_bfloat16* Alo,
                      const float* W, const float* al, const float* ar,
                      float* feat, float* outf, __nv_bfloat16* ohi, __nv_bfloat16* olo,
                      int N, const int* rowptr, const int* csrc, float* el, float* er,
                      __nv_bfloat16* whi, __nv_bfloat16* wlo) {
    constexpr int J = H * D;
    constexpr int J64 = (J + 63) / 64 * 64;
    prepw_k<<<(K * J64 + 255) / 256, 256>>>(W, whi, wlo, K, J, J64);
    cudaMemsetAsync(el, 0, (size_t)N * H * sizeof(float));
    cudaMemsetAsync(er, 0, (size_t)N * H * sizeof(float));
    dim3 grid(J64 / 64, (N + 127) / 128);
    gemm_mma<K, J, D><<<grid, 256>>>(Ahi, Alo, whi, wlo, al, ar, feat, el, er, N);
    agg_k<H, D, ACT, WM><<<(N * 32 + 255) / 256, 256>>>(rowptr, csrc, el, er, feat,
                                                        outf, ohi, olo, N);
}

extern "C" void kernel_launch(void* const* d_in, const int* in_sizes, int n_in,
                              void* d_out, int out_size) {
    const float* x    = (const float*)d_in[0];
    const int*   src  = (const int*)d_in[1];
    const int*   dst  = (const int*)d_in[2];
    const float* W00  = (const float*)d_in[3];
    const float* a00l = (const float*)d_in[4];
    const float* a00r = (const float*)d_in[5];
    const float* W01  = (const float*)d_in[6];
    const float* a01l = (const float*)d_in[7];
    const float* a01r = (const float*)d_in[8];
    const float* W0f  = (const float*)d_in[9];
    const float* a0fl = (const float*)d_in[10];
    const float* a0fr = (const float*)d_in[11];
    const float* W10  = (const float*)d_in[12];
    const float* a10l = (const float*)d_in[13];
    const float* a10r = (const float*)d_in[14];
    const float* W1f  = (const float*)d_in[15];
    const float* a1fl = (const float*)d_in[16];
    const float* a1fr = (const float*)d_in[17];
    const float* W1o  = (const float*)d_in[18];
    const float* a1ol = (const float*)d_in[19];
    const float* a1or = (const float*)d_in[20];
    float* out = (float*)d_out;

    const int N = in_sizes[0] / 256;
    const int E = in_sizes[1];

    float *feat, *el, *er;
    __nv_bfloat16 *xhi, *xlo, *hhi, *hlo, *whi, *wlo;
    int *deg, *rowptr, *wp, *bsum, *csrc;
    cudaGetSymbolAddress((void**)&feat, g_feat);
    cudaGetSymbolAddress((void**)&el, g_el);
    cudaGetSymbolAddress((void**)&er, g_er);
    cudaGetSymbolAddress((void**)&xhi, g_xhi);
    cudaGetSymbolAddress((void**)&xlo, g_xlo);
    cudaGetSymbolAddress((void**)&hhi, g_hhi);
    cudaGetSymbolAddress((void**)&hlo, g_hlo);
    cudaGetSymbolAddress((void**)&whi, g_whi);
    cudaGetSymbolAddress((void**)&wlo, g_wlo);
    cudaGetSymbolAddress((void**)&deg, g_deg);
    cudaGetSymbolAddress((void**)&rowptr, g_rowptr);
    cudaGetSymbolAddress((void**)&wp, g_wp);
    cudaGetSymbolAddress((void**)&bsum, g_bsum);
    cudaGetSymbolAddress((void**)&csrc, g_csrc);

    // ---- x split + dst-CSR build (shared by all layers) ----
    split_k<<<((long)N * 256 + 255) / 256, 256>>>(x, xhi, xlo, N * 256);
    zero_deg<<<(N + 255) / 256, 256>>>(deg, N);
    hist_k<<<(E + 255) / 256, 256>>>(dst, deg, E);
    int ntiles = (N + 1023) / 1024;
    scan_tiles<<<ntiles, 1024>>>(deg, rowptr, bsum, N);
    scan_bsum<<<1, 32>>>(bsum, ntiles);
    add_off<<<(N + 255) / 256, 256>>>(rowptr, wp, bsum, N, E);
    scatter_k<<<(E + 255) / 256, 256>>>(src, dst, wp, csrc, E);

    // ---- branch 0 ----
    run_layer<256, 4, 64, 1, 1>(xhi, xlo, W00, a00l, a00r, feat, nullptr, hhi, hlo,
                                N, rowptr, csrc, el, er, whi, wlo);
    run_layer<256, 1, 64, 1, 1>(hhi, hlo, W01, a01l, a01r, feat, nullptr, hhi, hlo,
                                N, rowptr, csrc, el, er, whi, wlo);
    run_layer<64, 1, 40, 0, 0>(hhi, hlo, W0f, a0fl, a0fr, feat, out, nullptr, nullptr,
                               N, rowptr, csrc, el, er, whi, wlo);

    // ---- branch 1 ----
    run_layer<256, 4, 64, 1, 1>(xhi, xlo, W10, a10l, a10r, feat, nullptr, hhi, hlo,
                                N, rowptr, csrc, el, er, whi, wlo);
    run_layer<256, 1, 64, 0, 1>(hhi, hlo, W1f, a1fl, a1fr, feat, nullptr, hhi, hlo,
                                N, rowptr, csrc, el, er, whi, wlo);
    run_layer<64, 1, 40, 1, 0>(hhi, hlo, W1o, a1ol, a1or, feat, out + (size_t)N * CC,
                               nullptr, nullptr, N, rowptr, csrc, el, er, whi, wlo);
}